// round 4
// baseline (speedup 1.0000x reference)
#include <cuda_runtime.h>
#include <math.h>
#include <stdint.h>

constexpr int Bb   = 2;
constexpr int Hh   = 16;
constexpr int Nn   = 2048;
constexpr int HDc  = 64;
constexpr int DIMd = 1024;
constexpr int Mrows = Bb * Nn;       // 4096
constexpr float ATTN_SCALE = 0.125f;

// Scratch buffers
__device__ float g_qh[Bb * Hh * Nn * HDc];   // Q heads (tf32 bits, pre-scaled)
__device__ float g_kh[Bb * Hh * Nn * HDc];   // K heads (tf32 bits)
__device__ float g_vh[Bb * Hh * Nn * HDc];   // V heads (tf32 bits)
__device__ float g_ao[Bb * Hh * Nn * HDc];   // attn out (tf32 bits)
__device__ float g_qt[Mrows * DIMd];         // tf32 copies of inputs
__device__ float g_kt[Mrows * DIMd];
__device__ float g_vt[Mrows * DIMd];
__device__ float g_wq[DIMd * DIMd];          // tf32 copies of weights
__device__ float g_wk[DIMd * DIMd];
__device__ float g_wv[DIMd * DIMd];
__device__ float g_wo[DIMd * DIMd];

__device__ __forceinline__ uint32_t tf32r(float x) {
    uint32_t y;
    asm("cvt.rna.tf32.f32 %0, %1;" : "=r"(y) : "f"(x));
    return y;
}

__device__ __forceinline__ void mma8(float* d, const uint32_t* a, const uint32_t* b) {
    asm volatile(
        "mma.sync.aligned.m16n8k8.row.col.f32.tf32.tf32.f32 "
        "{%0,%1,%2,%3}, {%4,%5,%6,%7}, {%8,%9}, {%0,%1,%2,%3};\n"
        : "+f"(d[0]), "+f"(d[1]), "+f"(d[2]), "+f"(d[3])
        : "r"(a[0]), "r"(a[1]), "r"(a[2]), "r"(a[3]), "r"(b[0]), "r"(b[1]));
}

__device__ __forceinline__ void cp16(uint32_t daddr, const void* src) {
    asm volatile("cp.async.cg.shared.global [%0], [%1], 16;\n"
                 :: "r"(daddr), "l"(src));
}
__device__ __forceinline__ void cp_commit() {
    asm volatile("cp.async.commit_group;\n");
}
template <int N>
__device__ __forceinline__ void cp_wait() {
    asm volatile("cp.async.wait_group %0;\n" :: "n"(N));
}

// ---------------------------------------------------------------------------
// Elementwise tf32 (RNA) pre-conversion
// ---------------------------------------------------------------------------
__global__ __launch_bounds__(256) void cvt_tf32(const float4* __restrict__ s,
                                                float4* __restrict__ d, int n4) {
    int i = blockIdx.x * 256 + threadIdx.x;
    if (i < n4) {
        float4 v = s[i];
        float4 o;
        o.x = __uint_as_float(tf32r(v.x));
        o.y = __uint_as_float(tf32r(v.y));
        o.z = __uint_as_float(tf32r(v.z));
        o.w = __uint_as_float(tf32r(v.w));
        d[i] = o;
    }
}

// ---------------------------------------------------------------------------
// Projection GEMM: C[m,n] = (sum_k A[m,k]*W[n,k] + bias[n]) * scale
// A, W tf32-rounded in gmem. 128x128x32 tiles, 4-stage cp.async pipeline,
// ONE __syncthreads per k-step. 256 threads, 8 warps (2x4), 64x32 per warp.
// ---------------------------------------------------------------------------
constexpr int SKA = 36;                        // smem k-stride words
constexpr int STG = 4;                         // pipeline stages
constexpr int PROJ_SMEM = 2 * STG * 128 * SKA * 4;  // 147456 B

template <bool SPLIT_IN, bool SPLIT_OUT, bool ROUND>
__device__ __forceinline__ void proj_body(
    const float* __restrict__ A, const float* __restrict__ W,
    const float* __restrict__ bias, float* __restrict__ C, float scale,
    float* smf)
{
    const int m0 = blockIdx.y * 128, n0 = blockIdx.x * 128;
    const int tid = threadIdx.x;
    const int w = tid >> 5, lane = tid & 31;
    const int gid = lane >> 2, tig = lane & 3;
    const int mbase = (w & 1) * 64;
    const int nbase = (w >> 1) * 32;

    const uint32_t su = (uint32_t)__cvta_generic_to_shared(smf);
    // Buffers: A stages 0..3 then W stages 0..3
    auto abuf = [&](int s) { return (const uint32_t*)smf + s * 128 * SKA; };
    auto wbuf = [&](int s) { return (const uint32_t*)smf + (STG + s) * 128 * SKA; };

    auto load_tiles = [&](int kt, int buf) {
        const int k0 = kt * 32;
        const uint32_t au = su + buf * 128 * SKA * 4;
        const uint32_t wu = su + (STG + buf) * 128 * SKA * 4;
#pragma unroll
        for (int t = 0; t < 4; t++) {
            const int idx = tid + t * 256;
            const int r = idx >> 3, c = (idx & 7) << 2;
            const float* ap;
            if (SPLIT_IN) {
                const int gm = m0 + r, gk = k0 + c;
                const int b = gm >> 11, tok = gm & (Nn - 1);
                const int h = gk >> 6, cc = gk & 63;
                ap = A + ((size_t)((b * Hh + h) * Nn + tok)) * HDc + cc;
            } else {
                ap = A + (size_t)(m0 + r) * DIMd + k0 + c;
            }
            cp16(au + (r * SKA + c) * 4, ap);
            cp16(wu + (r * SKA + c) * 4,
                 W + (size_t)(n0 + r) * DIMd + k0 + c);
        }
    };

    float c[4][4][4];
#pragma unroll
    for (int mi = 0; mi < 4; mi++)
#pragma unroll
        for (int ni = 0; ni < 4; ni++)
#pragma unroll
            for (int u = 0; u < 4; u++) c[mi][ni][u] = 0.f;

    load_tiles(0, 0); cp_commit();
    load_tiles(1, 1); cp_commit();
    load_tiles(2, 2); cp_commit();

    constexpr int ITERS = DIMd / 32;  // 32
    for (int kt = 0; kt < ITERS; kt++) {
        cp_wait<2>();          // group kt complete (kt+1, kt+2 may be pending)
        __syncthreads();       // data visible; all warps done with buf (kt-1)%STG
        if (kt + 3 < ITERS) load_tiles(kt + 3, (kt + 3) & (STG - 1));
        cp_commit();           // keep group accounting uniform

        const uint32_t* Ab = abuf(kt & (STG - 1));
        const uint32_t* Wb = wbuf(kt & (STG - 1));
#pragma unroll
        for (int kk = 0; kk < 32; kk += 8) {
            uint32_t af[4][4];
#pragma unroll
            for (int mi = 0; mi < 4; mi++) {
                const uint32_t* p = Ab + (mbase + mi * 16 + gid) * SKA + kk + tig;
                af[mi][0] = p[0];
                af[mi][1] = p[8 * SKA];
                af[mi][2] = p[4];
                af[mi][3] = p[8 * SKA + 4];
            }
            uint32_t bf[4][2];
#pragma unroll
            for (int ni = 0; ni < 4; ni++) {
                const uint32_t* p = Wb + (nbase + ni * 8 + gid) * SKA + kk + tig;
                bf[ni][0] = p[0];
                bf[ni][1] = p[4];
            }
#pragma unroll
            for (int mi = 0; mi < 4; mi++)
#pragma unroll
                for (int ni = 0; ni < 4; ni++)
                    mma8(c[mi][ni], af[mi], bf[ni]);
        }
    }

    // Epilogue
#pragma unroll
    for (int mi = 0; mi < 4; mi++) {
#pragma unroll
        for (int ni = 0; ni < 4; ni++) {
            const int n = n0 + nbase + ni * 8 + 2 * tig;
            const float bx = bias[n], by = bias[n + 1];
#pragma unroll
            for (int hr = 0; hr < 2; hr++) {
                const int m = m0 + mbase + mi * 16 + gid + hr * 8;
                float2 o;
                o.x = (c[mi][ni][hr * 2 + 0] + bx) * scale;
                o.y = (c[mi][ni][hr * 2 + 1] + by) * scale;
                if (ROUND) {
                    o.x = __uint_as_float(tf32r(o.x));
                    o.y = __uint_as_float(tf32r(o.y));
                }
                if (SPLIT_OUT) {
                    const int b = m >> 11, tok = m & (Nn - 1);
                    const int h = n >> 6, cc = n & 63;
                    *reinterpret_cast<float2*>(
                        C + ((size_t)((b * Hh + h) * Nn + tok)) * HDc + cc) = o;
                } else {
                    *reinterpret_cast<float2*>(C + (size_t)m * DIMd + n) = o;
                }
            }
        }
    }
}

__global__ __launch_bounds__(256) void qkv_proj(
    const float* aq, const float* ak, const float* av,
    const float* wq, const float* wk, const float* wv,
    const float* bq, const float* bk, const float* bv,
    float* cq, float* ck, float* cv)
{
    extern __shared__ float smf[];
    const int z = blockIdx.z;
    const float* A = (z == 0) ? aq : (z == 1) ? ak : av;
    const float* W = (z == 0) ? wq : (z == 1) ? wk : wv;
    const float* b = (z == 0) ? bq : (z == 1) ? bk : bv;
    float*       C = (z == 0) ? cq : (z == 1) ? ck : cv;
    const float scale = (z == 0) ? ATTN_SCALE : 1.0f;
    proj_body<false, true, true>(A, W, b, C, scale, smf);
}

__global__ __launch_bounds__(256) void o_proj(
    const float* A, const float* W, const float* b, float* C)
{
    extern __shared__ float smf[];
    proj_body<true, false, false>(A, W, b, C, 1.0f, smf);
}

// ---------------------------------------------------------------------------
// Causal flash attention: 128 q-rows/CTA, 256 threads (8 warps, each owns a
// 16x64 strip). Register softmax. K/V 64-row tiles, cp.async double-buffered,
// ONE __syncthreads per k-tile. Heavy tiles scheduled first.
// ---------------------------------------------------------------------------
constexpr int AST = 68;  // smem row stride (words)
constexpr int ATT_SMEM = (4 * 64 + 128) * AST * 4;  // 2K + 2V + P = 104448 B

__global__ __launch_bounds__(256, 2) void attn2(
    const float* __restrict__ Qg, const float* __restrict__ Kg,
    const float* __restrict__ Vg, float* __restrict__ Og)
{
    extern __shared__ float smf[];
    const uint32_t su = (uint32_t)__cvta_generic_to_shared(smf);
    const uint32_t ksu[2] = {su, su + 64 * AST * 4};
    const uint32_t vsu[2] = {su + 2 * 64 * AST * 4, su + 3 * 64 * AST * 4};
    const uint32_t* Ksb[2] = {(const uint32_t*)smf,
                              (const uint32_t*)smf + 64 * AST};
    const uint32_t* Vsb[2] = {(const uint32_t*)smf + 2 * 64 * AST,
                              (const uint32_t*)smf + 3 * 64 * AST};
    uint32_t* Psu = (uint32_t*)smf + 4 * 64 * AST;

    const int bh = blockIdx.y;
    const int qtile = (gridDim.x - 1) - blockIdx.x;  // heavy-first
    const int q0 = qtile * 128;
    const size_t base = (size_t)bh * Nn * HDc;

    const int tid = threadIdx.x;
    const int w = tid >> 5, lane = tid & 31;
    const int gid = lane >> 2, tig = lane & 3;
    const int mrow = w * 16;

    auto issueKV = [&](int t_kt, int buf) {
        const float* Kb = Kg + base + (size_t)(t_kt * 64) * HDc;
        const float* Vb = Vg + base + (size_t)(t_kt * 64) * HDc;
#pragma unroll
        for (int t = 0; t < 4; t++) {
            const int idx = tid + t * 256;
            const int r = idx >> 4, cc = (idx & 15) << 2;
            cp16(ksu[buf] + (r * AST + cc) * 4, Kb + r * HDc + cc);
            cp16(vsu[buf] + (r * AST + cc) * 4, Vb + r * HDc + cc);
        }
        cp_commit();
    };

    // Q fragments: rows q0+mrow+gid, +8; all 64 head cols (tf32 bits in gmem)
    uint32_t qf[8][4];
    {
        const uint32_t* Qu = (const uint32_t*)(Qg + base) +
                             (size_t)(q0 + mrow + gid) * HDc;
#pragma unroll
        for (int s = 0; s < 8; s++) {
            const int kc = s * 8 + tig;
            qf[s][0] = Qu[kc];
            qf[s][1] = Qu[8 * HDc + kc];
            qf[s][2] = Qu[kc + 4];
            qf[s][3] = Qu[8 * HDc + kc + 4];
        }
    }

    float o[8][4];
#pragma unroll
    for (int ni = 0; ni < 8; ni++)
#pragma unroll
        for (int u = 0; u < 4; u++) o[ni][u] = 0.f;
    float m0r = -1e30f, m1r = -1e30f, l0 = 0.f, l1 = 0.f;

    const int ktmax = 2 * qtile + 1;
    issueKV(0, 0);

    for (int kt = 0; kt <= ktmax; kt++) {
        const int cur = kt & 1;
        cp_wait<0>();      // tile kt resident
        __syncthreads();   // visible to all; all warps done with buf cur^1
        if (kt < ktmax) issueKV(kt + 1, cur ^ 1);

        // ---- S = Q K^T (16x64 per warp) ----
        float s4[8][4];
#pragma unroll
        for (int ni = 0; ni < 8; ni++)
#pragma unroll
            for (int u = 0; u < 4; u++) s4[ni][u] = 0.f;

        const uint32_t* Kb = Ksb[cur];
#pragma unroll
        for (int s = 0; s < 8; s++) {
            const int kk = s * 8;
            uint32_t bf[8][2];
#pragma unroll
            for (int ni = 0; ni < 8; ni++) {
                const uint32_t* p = Kb + (ni * 8 + gid) * AST + kk + tig;
                bf[ni][0] = p[0];
                bf[ni][1] = p[4];
            }
#pragma unroll
            for (int ni = 0; ni < 8; ni++)
                mma8(s4[ni], qf[s], bf[ni]);
        }

        // ---- causal mask (last two tiles only) ----
        if (kt >= 2 * qtile) {
            const int r0 = q0 + mrow + gid, r1 = r0 + 8;
            const int k0 = kt * 64;
#pragma unroll
            for (int ni = 0; ni < 8; ni++) {
                const int cc = k0 + ni * 8 + 2 * tig;
                if (cc > r0)     s4[ni][0] = -1e30f;
                if (cc + 1 > r0) s4[ni][1] = -1e30f;
                if (cc > r1)     s4[ni][2] = -1e30f;
                if (cc + 1 > r1) s4[ni][3] = -1e30f;
            }
        }

        // ---- register softmax (rows warp-local; quad reduction) ----
        float mx0 = -1e30f, mx1 = -1e30f;
#pragma unroll
        for (int ni = 0; ni < 8; ni++) {
            mx0 = fmaxf(mx0, fmaxf(s4[ni][0], s4[ni][1]));
            mx1 = fmaxf(mx1, fmaxf(s4[ni][2], s4[ni][3]));
        }
        mx0 = fmaxf(mx0, __shfl_xor_sync(0xffffffffu, mx0, 1));
        mx0 = fmaxf(mx0, __shfl_xor_sync(0xffffffffu, mx0, 2));
        mx1 = fmaxf(mx1, __shfl_xor_sync(0xffffffffu, mx1, 1));
        mx1 = fmaxf(mx1, __shfl_xor_sync(0xffffffffu, mx1, 2));
        const float mn0 = fmaxf(m0r, mx0);
        const float mn1 = fmaxf(m1r, mx1);
        const float f0 = __expf(m0r - mn0);
        const float f1 = __expf(m1r - mn1);
        m0r = mn0; m1r = mn1;

        float sum0 = 0.f, sum1 = 0.f;
        uint32_t* Pw = Psu + (mrow + gid) * AST + 2 * tig;
#pragma unroll
        for (int ni = 0; ni < 8; ni++) {
            const float e0 = __expf(s4[ni][0] - mn0);
            const float e1 = __expf(s4[ni][1] - mn0);
            const float e2 = __expf(s4[ni][2] - mn1);
            const float e3 = __expf(s4[ni][3] - mn1);
            sum0 += e0 + e1;
            sum1 += e2 + e3;
            uint2 pa, pb;
            pa.x = tf32r(e0); pa.y = tf32r(e1);
            pb.x = tf32r(e2); pb.y = tf32r(e3);
            *reinterpret_cast<uint2*>(Pw + ni * 8) = pa;
            *reinterpret_cast<uint2*>(Pw + 8 * AST + ni * 8) = pb;
        }
        sum0 += __shfl_xor_sync(0xffffffffu, sum0, 1);
        sum0 += __shfl_xor_sync(0xffffffffu, sum0, 2);
        sum1 += __shfl_xor_sync(0xffffffffu, sum1, 1);
        sum1 += __shfl_xor_sync(0xffffffffu, sum1, 2);
        l0 = l0 * f0 + sum0;
        l1 = l1 * f1 + sum1;

#pragma unroll
        for (int ni = 0; ni < 8; ni++) {
            o[ni][0] *= f0; o[ni][1] *= f0;
            o[ni][2] *= f1; o[ni][3] *= f1;
        }
        __syncwarp();

        // ---- O += P * V ----
        const uint32_t* Vb = Vsb[cur];
#pragma unroll
        for (int s = 0; s < 8; s++) {
            const int kk = s * 8;
            uint32_t af[4];
            const uint32_t* p = Psu + (mrow + gid) * AST + kk + tig;
            af[0] = p[0];
            af[1] = p[8 * AST];
            af[2] = p[4];
            af[3] = p[8 * AST + 4];
            uint32_t bf[8][2];
#pragma unroll
            for (int ni = 0; ni < 8; ni++) {
                const uint32_t* q = Vb + (kk + tig) * AST + ni * 8 + gid;
                bf[ni][0] = q[0];
                bf[ni][1] = q[4 * AST];
            }
#pragma unroll
            for (int ni = 0; ni < 8; ni++)
                mma8(o[ni], af, bf[ni]);
        }
    }

    // ---- finalize: divide by l, tf32-round (feeds O-proj), store ----
    {
        const float inv0 = 1.f / l0;
        const float inv1 = 1.f / l1;
        const int r0 = q0 + mrow + gid;
        uint32_t* Ou = (uint32_t*)(Og + base);
#pragma unroll
        for (int ni = 0; ni < 8; ni++) {
            const int cc = ni * 8 + 2 * tig;
            uint2 oa, ob;
            oa.x = tf32r(o[ni][0] * inv0);
            oa.y = tf32r(o[ni][1] * inv0);
            ob.x = tf32r(o[ni][2] * inv1);
            ob.y = tf32r(o[ni][3] * inv1);
            *reinterpret_cast<uint2*>(Ou + (size_t)r0 * HDc + cc) = oa;
            *reinterpret_cast<uint2*>(Ou + (size_t)(r0 + 8) * HDc + cc) = ob;
        }
    }
}

// ---------------------------------------------------------------------------
extern "C" void kernel_launch(void* const* d_in, const int* in_sizes, int n_in,
                              void* d_out, int out_size)
{
    const float* q  = (const float*)d_in[0];
    const float* k  = (const float*)d_in[1];
    const float* v  = (const float*)d_in[2];
    // d_in[3] = mask (tril; causality applied analytically)
    const float* Wq = (const float*)d_in[4];
    const float* bq = (const float*)d_in[5];
    const float* Wk = (const float*)d_in[6];
    const float* bk = (const float*)d_in[7];
    const float* Wv = (const float*)d_in[8];
    const float* bv = (const float*)d_in[9];
    const float* Wo = (const float*)d_in[10];
    const float* bo = (const float*)d_in[11];
    float* out = (float*)d_out;

    float *qh, *kh, *vh, *ao, *qt, *kt, *vt, *wq, *wk, *wv, *wo;
    cudaGetSymbolAddress((void**)&qh, g_qh);
    cudaGetSymbolAddress((void**)&kh, g_kh);
    cudaGetSymbolAddress((void**)&vh, g_vh);
    cudaGetSymbolAddress((void**)&ao, g_ao);
    cudaGetSymbolAddress((void**)&qt, g_qt);
    cudaGetSymbolAddress((void**)&kt, g_kt);
    cudaGetSymbolAddress((void**)&vt, g_vt);
    cudaGetSymbolAddress((void**)&wq, g_wq);
    cudaGetSymbolAddress((void**)&wk, g_wk);
    cudaGetSymbolAddress((void**)&wv, g_wv);
    cudaGetSymbolAddress((void**)&wo, g_wo);

    static int cfg = 0;
    if (!cfg) {
        cudaFuncSetAttribute(qkv_proj,
            cudaFuncAttributeMaxDynamicSharedMemorySize, PROJ_SMEM);
        cudaFuncSetAttribute(o_proj,
            cudaFuncAttributeMaxDynamicSharedMemorySize, PROJ_SMEM);
        cudaFuncSetAttribute(attn2,
            cudaFuncAttributeMaxDynamicSharedMemorySize, ATT_SMEM);
        cfg = 1;
    }

    // Pre-round inputs and weights to tf32 (RNA)
    const int n4_in = Mrows * DIMd / 4;
    const int n4_w  = DIMd * DIMd / 4;
    cvt_tf32<<<(n4_in + 255) / 256, 256>>>((const float4*)q, (float4*)qt, n4_in);
    cvt_tf32<<<(n4_in + 255) / 256, 256>>>((const float4*)k, (float4*)kt, n4_in);
    cvt_tf32<<<(n4_in + 255) / 256, 256>>>((const float4*)v, (float4*)vt, n4_in);
    cvt_tf32<<<(n4_w + 255) / 256, 256>>>((const float4*)Wq, (float4*)wq, n4_w);
    cvt_tf32<<<(n4_w + 255) / 256, 256>>>((const float4*)Wk, (float4*)wk, n4_w);
    cvt_tf32<<<(n4_w + 255) / 256, 256>>>((const float4*)Wv, (float4*)wv, n4_w);
    cvt_tf32<<<(n4_w + 255) / 256, 256>>>((const float4*)Wo, (float4*)wo, n4_w);

    // Fused QKV projections (Q pre-scaled by ATTN_SCALE in epilogue)
    qkv_proj<<<dim3(DIMd / 128, Mrows / 128, 3), 256, PROJ_SMEM>>>(
        qt, kt, vt, wq, wk, wv, bq, bk, bv, qh, kh, vh);

    // Attention: 128 q-rows per CTA, heavy tiles first
    attn2<<<dim3(Nn / 128, Bb * Hh), 256, ATT_SMEM>>>(qh, kh, vh, ao);

    // Output projection
    o_proj<<<dim3(DIMd / 128, Mrows / 128), 256, PROJ_SMEM>>>(ao, wo, bo, out);
}

// round 5
// speedup vs baseline: 1.0062x; 1.0062x over previous
#include <cuda_runtime.h>
#include <math.h>
#include <stdint.h>

constexpr int Bb   = 2;
constexpr int Hh   = 16;
constexpr int Nn   = 2048;
constexpr int HDc  = 64;
constexpr int DIMd = 1024;
constexpr int Mrows = Bb * Nn;       // 4096
constexpr float ATTN_SCALE = 0.125f;

// Scratch buffers
__device__ float g_qh[Bb * Hh * Nn * HDc];   // Q heads (tf32 bits, pre-scaled)
__device__ float g_kh[Bb * Hh * Nn * HDc];   // K heads (tf32 bits)
__device__ float g_vh[Bb * Hh * Nn * HDc];   // V heads (tf32 bits)
__device__ float g_ao[Bb * Hh * Nn * HDc];   // attn out (tf32 bits)
__device__ float g_qt[Mrows * DIMd];         // tf32 copies of inputs
__device__ float g_kt[Mrows * DIMd];
__device__ float g_vt[Mrows * DIMd];
__device__ float g_wq[DIMd * DIMd];          // tf32 copies of weights
__device__ float g_wk[DIMd * DIMd];
__device__ float g_wv[DIMd * DIMd];
__device__ float g_wo[DIMd * DIMd];

__device__ __forceinline__ uint32_t tf32r(float x) {
    uint32_t y;
    asm("cvt.rna.tf32.f32 %0, %1;" : "=r"(y) : "f"(x));
    return y;
}

__device__ __forceinline__ void mma8(float* d, const uint32_t* a, const uint32_t* b) {
    asm volatile(
        "mma.sync.aligned.m16n8k8.row.col.f32.tf32.tf32.f32 "
        "{%0,%1,%2,%3}, {%4,%5,%6,%7}, {%8,%9}, {%0,%1,%2,%3};\n"
        : "+f"(d[0]), "+f"(d[1]), "+f"(d[2]), "+f"(d[3])
        : "r"(a[0]), "r"(a[1]), "r"(a[2]), "r"(a[3]), "r"(b[0]), "r"(b[1]));
}

__device__ __forceinline__ void cp16(uint32_t daddr, const void* src) {
    asm volatile("cp.async.cg.shared.global [%0], [%1], 16;\n"
                 :: "r"(daddr), "l"(src));
}
__device__ __forceinline__ void cp_commit() {
    asm volatile("cp.async.commit_group;\n");
}
template <int N>
__device__ __forceinline__ void cp_wait() {
    asm volatile("cp.async.wait_group %0;\n" :: "n"(N));
}

// ---------------------------------------------------------------------------
// Elementwise tf32 (RNA) pre-conversion
// ---------------------------------------------------------------------------
__global__ __launch_bounds__(256) void cvt_tf32(const float4* __restrict__ s,
                                                float4* __restrict__ d, int n4) {
    int i = blockIdx.x * 256 + threadIdx.x;
    if (i < n4) {
        float4 v = s[i];
        float4 o;
        o.x = __uint_as_float(tf32r(v.x));
        o.y = __uint_as_float(tf32r(v.y));
        o.z = __uint_as_float(tf32r(v.z));
        o.w = __uint_as_float(tf32r(v.w));
        d[i] = o;
    }
}

// ---------------------------------------------------------------------------
// Projection GEMM (R3 proven config): 128x128x32 tiles, 2-stage cp.async
// double buffer, 73.7KB smem -> 2 CTAs/SM. 256 threads, 8 warps (2x4),
// 64x32 per warp, 4x4 m16n8k8 tiles.
// ---------------------------------------------------------------------------
constexpr int SKA = 36;                        // smem k-stride words
constexpr int PROJ_SMEM = 4 * 128 * SKA * 4;   // 73728 B

template <bool SPLIT_IN, bool SPLIT_OUT, bool ROUND>
__device__ __forceinline__ void proj_body(
    const float* __restrict__ A, const float* __restrict__ W,
    const float* __restrict__ bias, float* __restrict__ C, float scale,
    float* smf)
{
    const int m0 = blockIdx.y * 128, n0 = blockIdx.x * 128;
    const int tid = threadIdx.x;
    const int w = tid >> 5, lane = tid & 31;
    const int gid = lane >> 2, tig = lane & 3;
    const int mbase = (w & 1) * 64;
    const int nbase = (w >> 1) * 32;

    const uint32_t* Asb[2] = {(const uint32_t*)smf,
                              (const uint32_t*)smf + 128 * SKA};
    const uint32_t* Wsb[2] = {(const uint32_t*)smf + 2 * 128 * SKA,
                              (const uint32_t*)smf + 3 * 128 * SKA};
    const uint32_t su = (uint32_t)__cvta_generic_to_shared(smf);
    const uint32_t asu[2] = {su, su + 128 * SKA * 4};
    const uint32_t wsu[2] = {su + 2 * 128 * SKA * 4, su + 3 * 128 * SKA * 4};

    auto load_tiles = [&](int kt, int buf) {
        const int k0 = kt * 32;
#pragma unroll
        for (int t = 0; t < 4; t++) {
            const int idx = tid + t * 256;
            const int r = idx >> 3, c = (idx & 7) << 2;
            const float* ap;
            if (SPLIT_IN) {
                const int gm = m0 + r, gk = k0 + c;
                const int b = gm >> 11, tok = gm & (Nn - 1);
                const int h = gk >> 6, cc = gk & 63;
                ap = A + ((size_t)((b * Hh + h) * Nn + tok)) * HDc + cc;
            } else {
                ap = A + (size_t)(m0 + r) * DIMd + k0 + c;
            }
            cp16(asu[buf] + (r * SKA + c) * 4, ap);
            cp16(wsu[buf] + (r * SKA + c) * 4,
                 W + (size_t)(n0 + r) * DIMd + k0 + c);
        }
        cp_commit();
    };

    float c[4][4][4];
#pragma unroll
    for (int mi = 0; mi < 4; mi++)
#pragma unroll
        for (int ni = 0; ni < 4; ni++)
#pragma unroll
            for (int u = 0; u < 4; u++) c[mi][ni][u] = 0.f;

    load_tiles(0, 0);
    constexpr int ITERS = DIMd / 32;  // 32
    for (int kt = 0; kt < ITERS; kt++) {
        const int cur = kt & 1;
        if (kt + 1 < ITERS) { load_tiles(kt + 1, cur ^ 1); cp_wait<1>(); }
        else                { cp_wait<0>(); }
        __syncthreads();

        const uint32_t* Ab = Asb[cur];
        const uint32_t* Wb = Wsb[cur];
#pragma unroll
        for (int kk = 0; kk < 32; kk += 8) {
            uint32_t af[4][4];
#pragma unroll
            for (int mi = 0; mi < 4; mi++) {
                const uint32_t* p = Ab + (mbase + mi * 16 + gid) * SKA + kk + tig;
                af[mi][0] = p[0];
                af[mi][1] = p[8 * SKA];
                af[mi][2] = p[4];
                af[mi][3] = p[8 * SKA + 4];
            }
            uint32_t bf[4][2];
#pragma unroll
            for (int ni = 0; ni < 4; ni++) {
                const uint32_t* p = Wb + (nbase + ni * 8 + gid) * SKA + kk + tig;
                bf[ni][0] = p[0];
                bf[ni][1] = p[4];
            }
#pragma unroll
            for (int mi = 0; mi < 4; mi++)
#pragma unroll
                for (int ni = 0; ni < 4; ni++)
                    mma8(c[mi][ni], af[mi], bf[ni]);
        }
        __syncthreads();
    }

    // Epilogue
#pragma unroll
    for (int mi = 0; mi < 4; mi++) {
#pragma unroll
        for (int ni = 0; ni < 4; ni++) {
            const int n = n0 + nbase + ni * 8 + 2 * tig;
            const float bx = bias[n], by = bias[n + 1];
#pragma unroll
            for (int hr = 0; hr < 2; hr++) {
                const int m = m0 + mbase + mi * 16 + gid + hr * 8;
                float2 o;
                o.x = (c[mi][ni][hr * 2 + 0] + bx) * scale;
                o.y = (c[mi][ni][hr * 2 + 1] + by) * scale;
                if (ROUND) {
                    o.x = __uint_as_float(tf32r(o.x));
                    o.y = __uint_as_float(tf32r(o.y));
                }
                if (SPLIT_OUT) {
                    const int b = m >> 11, tok = m & (Nn - 1);
                    const int h = n >> 6, cc = n & 63;
                    *reinterpret_cast<float2*>(
                        C + ((size_t)((b * Hh + h) * Nn + tok)) * HDc + cc) = o;
                } else {
                    *reinterpret_cast<float2*>(C + (size_t)m * DIMd + n) = o;
                }
            }
        }
    }
}

__global__ __launch_bounds__(256) void qkv_proj(
    const float* aq, const float* ak, const float* av,
    const float* wq, const float* wk, const float* wv,
    const float* bq, const float* bk, const float* bv,
    float* cq, float* ck, float* cv)
{
    extern __shared__ float smf[];
    const int z = blockIdx.z;
    const float* A = (z == 0) ? aq : (z == 1) ? ak : av;
    const float* W = (z == 0) ? wq : (z == 1) ? wk : wv;
    const float* b = (z == 0) ? bq : (z == 1) ? bk : bv;
    float*       C = (z == 0) ? cq : (z == 1) ? ck : cv;
    const float scale = (z == 0) ? ATTN_SCALE : 1.0f;
    proj_body<false, true, true>(A, W, b, C, scale, smf);
}

__global__ __launch_bounds__(256) void o_proj(
    const float* A, const float* W, const float* b, float* C)
{
    extern __shared__ float smf[];
    proj_body<true, false, false>(A, W, b, C, 1.0f, smf);
}

// ---------------------------------------------------------------------------
// Causal flash attention (R4 config): 128 q-rows/CTA, 256 threads (8 warps,
// each owns a 16x64 strip). Register softmax. K/V 64-row tiles, cp.async
// double-buffered, ONE __syncthreads per k-tile. Heavy tiles first.
// ---------------------------------------------------------------------------
constexpr int AST = 68;  // smem row stride (words)
constexpr int ATT_SMEM = (4 * 64 + 128) * AST * 4;  // 2K + 2V + P = 104448 B

__global__ __launch_bounds__(256, 2) void attn2(
    const float* __restrict__ Qg, const float* __restrict__ Kg,
    const float* __restrict__ Vg, float* __restrict__ Og)
{
    extern __shared__ float smf[];
    const uint32_t su = (uint32_t)__cvta_generic_to_shared(smf);
    const uint32_t ksu[2] = {su, su + 64 * AST * 4};
    const uint32_t vsu[2] = {su + 2 * 64 * AST * 4, su + 3 * 64 * AST * 4};
    const uint32_t* Ksb[2] = {(const uint32_t*)smf,
                              (const uint32_t*)smf + 64 * AST};
    const uint32_t* Vsb[2] = {(const uint32_t*)smf + 2 * 64 * AST,
                              (const uint32_t*)smf + 3 * 64 * AST};
    uint32_t* Psu = (uint32_t*)smf + 4 * 64 * AST;

    const int bh = blockIdx.y;
    const int qtile = (gridDim.x - 1) - blockIdx.x;  // heavy-first
    const int q0 = qtile * 128;
    const size_t base = (size_t)bh * Nn * HDc;

    const int tid = threadIdx.x;
    const int w = tid >> 5, lane = tid & 31;
    const int gid = lane >> 2, tig = lane & 3;
    const int mrow = w * 16;

    auto issueKV = [&](int t_kt, int buf) {
        const float* Kb = Kg + base + (size_t)(t_kt * 64) * HDc;
        const float* Vb = Vg + base + (size_t)(t_kt * 64) * HDc;
#pragma unroll
        for (int t = 0; t < 4; t++) {
            const int idx = tid + t * 256;
            const int r = idx >> 4, cc = (idx & 15) << 2;
            cp16(ksu[buf] + (r * AST + cc) * 4, Kb + r * HDc + cc);
            cp16(vsu[buf] + (r * AST + cc) * 4, Vb + r * HDc + cc);
        }
        cp_commit();
    };

    // Q fragments: rows q0+mrow+gid, +8; all 64 head cols (tf32 bits in gmem)
    uint32_t qf[8][4];
    {
        const uint32_t* Qu = (const uint32_t*)(Qg + base) +
                             (size_t)(q0 + mrow + gid) * HDc;
#pragma unroll
        for (int s = 0; s < 8; s++) {
            const int kc = s * 8 + tig;
            qf[s][0] = Qu[kc];
            qf[s][1] = Qu[8 * HDc + kc];
            qf[s][2] = Qu[kc + 4];
            qf[s][3] = Qu[8 * HDc + kc + 4];
        }
    }

    float o[8][4];
#pragma unroll
    for (int ni = 0; ni < 8; ni++)
#pragma unroll
        for (int u = 0; u < 4; u++) o[ni][u] = 0.f;
    float m0r = -1e30f, m1r = -1e30f, l0 = 0.f, l1 = 0.f;

    const int ktmax = 2 * qtile + 1;
    issueKV(0, 0);

    for (int kt = 0; kt <= ktmax; kt++) {
        const int cur = kt & 1;
        cp_wait<0>();      // tile kt resident
        __syncthreads();   // visible to all; all warps done with buf cur^1
        if (kt < ktmax) issueKV(kt + 1, cur ^ 1);

        // ---- S = Q K^T (16x64 per warp) ----
        float s4[8][4];
#pragma unroll
        for (int ni = 0; ni < 8; ni++)
#pragma unroll
            for (int u = 0; u < 4; u++) s4[ni][u] = 0.f;

        const uint32_t* Kb = Ksb[cur];
#pragma unroll
        for (int s = 0; s < 8; s++) {
            const int kk = s * 8;
            uint32_t bf[8][2];
#pragma unroll
            for (int ni = 0; ni < 8; ni++) {
                const uint32_t* p = Kb + (ni * 8 + gid) * AST + kk + tig;
                bf[ni][0] = p[0];
                bf[ni][1] = p[4];
            }
#pragma unroll
            for (int ni = 0; ni < 8; ni++)
                mma8(s4[ni], qf[s], bf[ni]);
        }

        // ---- causal mask (last two tiles only) ----
        if (kt >= 2 * qtile) {
            const int r0 = q0 + mrow + gid, r1 = r0 + 8;
            const int k0 = kt * 64;
#pragma unroll
            for (int ni = 0; ni < 8; ni++) {
                const int cc = k0 + ni * 8 + 2 * tig;
                if (cc > r0)     s4[ni][0] = -1e30f;
                if (cc + 1 > r0) s4[ni][1] = -1e30f;
                if (cc > r1)     s4[ni][2] = -1e30f;
                if (cc + 1 > r1) s4[ni][3] = -1e30f;
            }
        }

        // ---- register softmax (rows warp-local; quad reduction) ----
        float mx0 = -1e30f, mx1 = -1e30f;
#pragma unroll
        for (int ni = 0; ni < 8; ni++) {
            mx0 = fmaxf(mx0, fmaxf(s4[ni][0], s4[ni][1]));
            mx1 = fmaxf(mx1, fmaxf(s4[ni][2], s4[ni][3]));
        }
        mx0 = fmaxf(mx0, __shfl_xor_sync(0xffffffffu, mx0, 1));
        mx0 = fmaxf(mx0, __shfl_xor_sync(0xffffffffu, mx0, 2));
        mx1 = fmaxf(mx1, __shfl_xor_sync(0xffffffffu, mx1, 1));
        mx1 = fmaxf(mx1, __shfl_xor_sync(0xffffffffu, mx1, 2));
        const float mn0 = fmaxf(m0r, mx0);
        const float mn1 = fmaxf(m1r, mx1);
        const float f0 = __expf(m0r - mn0);
        const float f1 = __expf(m1r - mn1);
        m0r = mn0; m1r = mn1;

        float sum0 = 0.f, sum1 = 0.f;
        uint32_t* Pw = Psu + (mrow + gid) * AST + 2 * tig;
#pragma unroll
        for (int ni = 0; ni < 8; ni++) {
            const float e0 = __expf(s4[ni][0] - mn0);
            const float e1 = __expf(s4[ni][1] - mn0);
            const float e2 = __expf(s4[ni][2] - mn1);
            const float e3 = __expf(s4[ni][3] - mn1);
            sum0 += e0 + e1;
            sum1 += e2 + e3;
            uint2 pa, pb;
            pa.x = tf32r(e0); pa.y = tf32r(e1);
            pb.x = tf32r(e2); pb.y = tf32r(e3);
            *reinterpret_cast<uint2*>(Pw + ni * 8) = pa;
            *reinterpret_cast<uint2*>(Pw + 8 * AST + ni * 8) = pb;
        }
        sum0 += __shfl_xor_sync(0xffffffffu, sum0, 1);
        sum0 += __shfl_xor_sync(0xffffffffu, sum0, 2);
        sum1 += __shfl_xor_sync(0xffffffffu, sum1, 1);
        sum1 += __shfl_xor_sync(0xffffffffu, sum1, 2);
        l0 = l0 * f0 + sum0;
        l1 = l1 * f1 + sum1;

#pragma unroll
        for (int ni = 0; ni < 8; ni++) {
            o[ni][0] *= f0; o[ni][1] *= f0;
            o[ni][2] *= f1; o[ni][3] *= f1;
        }
        __syncwarp();

        // ---- O += P * V ----
        const uint32_t* Vb = Vsb[cur];
#pragma unroll
        for (int s = 0; s < 8; s++) {
            const int kk = s * 8;
            uint32_t af[4];
            const uint32_t* p = Psu + (mrow + gid) * AST + kk + tig;
            af[0] = p[0];
            af[1] = p[8 * AST];
            af[2] = p[4];
            af[3] = p[8 * AST + 4];
            uint32_t bf[8][2];
#pragma unroll
            for (int ni = 0; ni < 8; ni++) {
                const uint32_t* q = Vb + (kk + tig) * AST + ni * 8 + gid;
                bf[ni][0] = q[0];
                bf[ni][1] = q[4 * AST];
            }
#pragma unroll
            for (int ni = 0; ni < 8; ni++)
                mma8(o[ni], af, bf[ni]);
        }
    }

    // ---- finalize: divide by l, tf32-round (feeds O-proj), store ----
    {
        const float inv0 = 1.f / l0;
        const float inv1 = 1.f / l1;
        const int r0 = q0 + mrow + gid;
        uint32_t* Ou = (uint32_t*)(Og + base);
#pragma unroll
        for (int ni = 0; ni < 8; ni++) {
            const int cc = ni * 8 + 2 * tig;
            uint2 oa, ob;
            oa.x = tf32r(o[ni][0] * inv0);
            oa.y = tf32r(o[ni][1] * inv0);
            ob.x = tf32r(o[ni][2] * inv1);
            ob.y = tf32r(o[ni][3] * inv1);
            *reinterpret_cast<uint2*>(Ou + (size_t)r0 * HDc + cc) = oa;
            *reinterpret_cast<uint2*>(Ou + (size_t)(r0 + 8) * HDc + cc) = ob;
        }
    }
}

// ---------------------------------------------------------------------------
extern "C" void kernel_launch(void* const* d_in, const int* in_sizes, int n_in,
                              void* d_out, int out_size)
{
    const float* q  = (const float*)d_in[0];
    const float* k  = (const float*)d_in[1];
    const float* v  = (const float*)d_in[2];
    // d_in[3] = mask (tril; causality applied analytically)
    const float* Wq = (const float*)d_in[4];
    const float* bq = (const float*)d_in[5];
    const float* Wk = (const float*)d_in[6];
    const float* bk = (const float*)d_in[7];
    const float* Wv = (const float*)d_in[8];
    const float* bv = (const float*)d_in[9];
    const float* Wo = (const float*)d_in[10];
    const float* bo = (const float*)d_in[11];
    float* out = (float*)d_out;

    float *qh, *kh, *vh, *ao, *qt, *kt, *vt, *wq, *wk, *wv, *wo;
    cudaGetSymbolAddress((void**)&qh, g_qh);
    cudaGetSymbolAddress((void**)&kh, g_kh);
    cudaGetSymbolAddress((void**)&vh, g_vh);
    cudaGetSymbolAddress((void**)&ao, g_ao);
    cudaGetSymbolAddress((void**)&qt, g_qt);
    cudaGetSymbolAddress((void**)&kt, g_kt);
    cudaGetSymbolAddress((void**)&vt, g_vt);
    cudaGetSymbolAddress((void**)&wq, g_wq);
    cudaGetSymbolAddress((void**)&wk, g_wk);
    cudaGetSymbolAddress((void**)&wv, g_wv);
    cudaGetSymbolAddress((void**)&wo, g_wo);

    static int cfg = 0;
    if (!cfg) {
        cudaFuncSetAttribute(qkv_proj,
            cudaFuncAttributeMaxDynamicSharedMemorySize, PROJ_SMEM);
        cudaFuncSetAttribute(o_proj,
            cudaFuncAttributeMaxDynamicSharedMemorySize, PROJ_SMEM);
        cudaFuncSetAttribute(attn2,
            cudaFuncAttributeMaxDynamicSharedMemorySize, ATT_SMEM);
        cfg = 1;
    }

    // Pre-round inputs and weights to tf32 (RNA)
    const int n4_in = Mrows * DIMd / 4;
    const int n4_w  = DIMd * DIMd / 4;
    cvt_tf32<<<(n4_in + 255) / 256, 256>>>((const float4*)q, (float4*)qt, n4_in);
    cvt_tf32<<<(n4_in + 255) / 256, 256>>>((const float4*)k, (float4*)kt, n4_in);
    cvt_tf32<<<(n4_in + 255) / 256, 256>>>((const float4*)v, (float4*)vt, n4_in);
    cvt_tf32<<<(n4_w + 255) / 256, 256>>>((const float4*)Wq, (float4*)wq, n4_w);
    cvt_tf32<<<(n4_w + 255) / 256, 256>>>((const float4*)Wk, (float4*)wk, n4_w);
    cvt_tf32<<<(n4_w + 255) / 256, 256>>>((const float4*)Wv, (float4*)wv, n4_w);
    cvt_tf32<<<(n4_w + 255) / 256, 256>>>((const float4*)Wo, (float4*)wo, n4_w);

    // Fused QKV projections (Q pre-scaled by ATTN_SCALE in epilogue)
    qkv_proj<<<dim3(DIMd / 128, Mrows / 128, 3), 256, PROJ_SMEM>>>(
        qt, kt, vt, wq, wk, wv, bq, bk, bv, qh, kh, vh);

    // Attention: 128 q-rows per CTA, heavy tiles first
    attn2<<<dim3(Nn / 128, Bb * Hh), 256, ATT_SMEM>>>(qh, kh, vh, ao);

    // Output projection
    o_proj<<<dim3(DIMd / 128, Mrows / 128), 256, PROJ_SMEM>>>(ao, wo, bo, out);
}

// round 6
// speedup vs baseline: 1.0323x; 1.0259x over previous
#include <cuda_runtime.h>
#include <math.h>
#include <stdint.h>

constexpr int Bb   = 2;
constexpr int Hh   = 16;
constexpr int Nn   = 2048;
constexpr int HDc  = 64;
constexpr int DIMd = 1024;
constexpr int Mrows = Bb * Nn;       // 4096
constexpr float ATTN_SCALE = 0.125f;

// Scratch buffers
__device__ float g_qh[Bb * Hh * Nn * HDc];   // Q heads (tf32 bits, pre-scaled)
__device__ float g_kh[Bb * Hh * Nn * HDc];   // K heads (tf32 bits)
__device__ float g_vh[Bb * Hh * Nn * HDc];   // V heads (tf32 bits)
__device__ float g_ao[Bb * Hh * Nn * HDc];   // attn out (tf32 bits)
__device__ float g_qt[Mrows * DIMd];         // tf32 copies of inputs
__device__ float g_kt[Mrows * DIMd];
__device__ float g_vt[Mrows * DIMd];
__device__ float g_wq[DIMd * DIMd];          // tf32 copies of weights
__device__ float g_wk[DIMd * DIMd];
__device__ float g_wv[DIMd * DIMd];
__device__ float g_wo[DIMd * DIMd];

__device__ __forceinline__ uint32_t tf32r(float x) {
    uint32_t y;
    asm("cvt.rna.tf32.f32 %0, %1;" : "=r"(y) : "f"(x));
    return y;
}

__device__ __forceinline__ void mma8(float* d, const uint32_t* a, const uint32_t* b) {
    asm volatile(
        "mma.sync.aligned.m16n8k8.row.col.f32.tf32.tf32.f32 "
        "{%0,%1,%2,%3}, {%4,%5,%6,%7}, {%8,%9}, {%0,%1,%2,%3};\n"
        : "+f"(d[0]), "+f"(d[1]), "+f"(d[2]), "+f"(d[3])
        : "r"(a[0]), "r"(a[1]), "r"(a[2]), "r"(a[3]), "r"(b[0]), "r"(b[1]));
}

__device__ __forceinline__ void cp16(uint32_t daddr, const void* src) {
    asm volatile("cp.async.cg.shared.global [%0], [%1], 16;\n"
                 :: "r"(daddr), "l"(src));
}
__device__ __forceinline__ void cp_commit() {
    asm volatile("cp.async.commit_group;\n");
}
template <int N>
__device__ __forceinline__ void cp_wait() {
    asm volatile("cp.async.wait_group %0;\n" :: "n"(N));
}

// ---------------------------------------------------------------------------
// Fused tf32 (RNA) pre-conversion for all 7 tensors (one launch).
// z = 0..2: inputs (1M float4 each); z = 3..6: weights (256K float4 each).
// ---------------------------------------------------------------------------
__global__ __launch_bounds__(256) void cvt_all(
    const float4* q, const float4* k, const float4* v,
    const float4* wq, const float4* wk, const float4* wv, const float4* wo,
    float4* qt, float4* kt, float4* vt,
    float4* dwq, float4* dwk, float4* dwv, float4* dwo)
{
    const int z = blockIdx.z;
    const int n4 = (z < 3) ? (Mrows * DIMd / 4) : (DIMd * DIMd / 4);
    const int i = blockIdx.x * 256 + threadIdx.x;
    if (i >= n4) return;
    const float4* s;
    float4* d;
    switch (z) {
        case 0: s = q;  d = qt;  break;
        case 1: s = k;  d = kt;  break;
        case 2: s = v;  d = vt;  break;
        case 3: s = wq; d = dwq; break;
        case 4: s = wk; d = dwk; break;
        case 5: s = wv; d = dwv; break;
        default: s = wo; d = dwo; break;
    }
    float4 x = s[i];
    float4 o;
    o.x = __uint_as_float(tf32r(x.x));
    o.y = __uint_as_float(tf32r(x.y));
    o.z = __uint_as_float(tf32r(x.z));
    o.w = __uint_as_float(tf32r(x.w));
    d[i] = o;
}

// ---------------------------------------------------------------------------
// Projection GEMM (R3 proven config): 128x128x32 tiles, 2-stage cp.async
// double buffer, 73.7KB smem -> 2 CTAs/SM. 256 threads, 8 warps (2x4),
// 64x32 per warp, 4x4 m16n8k8 tiles.
// ---------------------------------------------------------------------------
constexpr int SKA = 36;                        // smem k-stride words
constexpr int PROJ_SMEM = 4 * 128 * SKA * 4;   // 73728 B

template <bool SPLIT_IN, bool SPLIT_OUT, bool ROUND>
__device__ __forceinline__ void proj_body(
    const float* __restrict__ A, const float* __restrict__ W,
    const float* __restrict__ bias, float* __restrict__ C, float scale,
    float* smf)
{
    const int m0 = blockIdx.y * 128, n0 = blockIdx.x * 128;
    const int tid = threadIdx.x;
    const int w = tid >> 5, lane = tid & 31;
    const int gid = lane >> 2, tig = lane & 3;
    const int mbase = (w & 1) * 64;
    const int nbase = (w >> 1) * 32;

    const uint32_t* Asb[2] = {(const uint32_t*)smf,
                              (const uint32_t*)smf + 128 * SKA};
    const uint32_t* Wsb[2] = {(const uint32_t*)smf + 2 * 128 * SKA,
                              (const uint32_t*)smf + 3 * 128 * SKA};
    const uint32_t su = (uint32_t)__cvta_generic_to_shared(smf);
    const uint32_t asu[2] = {su, su + 128 * SKA * 4};
    const uint32_t wsu[2] = {su + 2 * 128 * SKA * 4, su + 3 * 128 * SKA * 4};

    auto load_tiles = [&](int kt, int buf) {
        const int k0 = kt * 32;
#pragma unroll
        for (int t = 0; t < 4; t++) {
            const int idx = tid + t * 256;
            const int r = idx >> 3, c = (idx & 7) << 2;
            const float* ap;
            if (SPLIT_IN) {
                const int gm = m0 + r, gk = k0 + c;
                const int b = gm >> 11, tok = gm & (Nn - 1);
                const int h = gk >> 6, cc = gk & 63;
                ap = A + ((size_t)((b * Hh + h) * Nn + tok)) * HDc + cc;
            } else {
                ap = A + (size_t)(m0 + r) * DIMd + k0 + c;
            }
            cp16(asu[buf] + (r * SKA + c) * 4, ap);
            cp16(wsu[buf] + (r * SKA + c) * 4,
                 W + (size_t)(n0 + r) * DIMd + k0 + c);
        }
        cp_commit();
    };

    float c[4][4][4];
#pragma unroll
    for (int mi = 0; mi < 4; mi++)
#pragma unroll
        for (int ni = 0; ni < 4; ni++)
#pragma unroll
            for (int u = 0; u < 4; u++) c[mi][ni][u] = 0.f;

    load_tiles(0, 0);
    constexpr int ITERS = DIMd / 32;  // 32
    for (int kt = 0; kt < ITERS; kt++) {
        const int cur = kt & 1;
        if (kt + 1 < ITERS) { load_tiles(kt + 1, cur ^ 1); cp_wait<1>(); }
        else                { cp_wait<0>(); }
        __syncthreads();

        const uint32_t* Ab = Asb[cur];
        const uint32_t* Wb = Wsb[cur];
#pragma unroll
        for (int kk = 0; kk < 32; kk += 8) {
            uint32_t af[4][4];
#pragma unroll
            for (int mi = 0; mi < 4; mi++) {
                const uint32_t* p = Ab + (mbase + mi * 16 + gid) * SKA + kk + tig;
                af[mi][0] = p[0];
                af[mi][1] = p[8 * SKA];
                af[mi][2] = p[4];
                af[mi][3] = p[8 * SKA + 4];
            }
            uint32_t bf[4][2];
#pragma unroll
            for (int ni = 0; ni < 4; ni++) {
                const uint32_t* p = Wb + (nbase + ni * 8 + gid) * SKA + kk + tig;
                bf[ni][0] = p[0];
                bf[ni][1] = p[4];
            }
#pragma unroll
            for (int mi = 0; mi < 4; mi++)
#pragma unroll
                for (int ni = 0; ni < 4; ni++)
                    mma8(c[mi][ni], af[mi], bf[ni]);
        }
        __syncthreads();
    }

    // Epilogue
#pragma unroll
    for (int mi = 0; mi < 4; mi++) {
#pragma unroll
        for (int ni = 0; ni < 4; ni++) {
            const int n = n0 + nbase + ni * 8 + 2 * tig;
            const float bx = bias[n], by = bias[n + 1];
#pragma unroll
            for (int hr = 0; hr < 2; hr++) {
                const int m = m0 + mbase + mi * 16 + gid + hr * 8;
                float2 o;
                o.x = (c[mi][ni][hr * 2 + 0] + bx) * scale;
                o.y = (c[mi][ni][hr * 2 + 1] + by) * scale;
                if (ROUND) {
                    o.x = __uint_as_float(tf32r(o.x));
                    o.y = __uint_as_float(tf32r(o.y));
                }
                if (SPLIT_OUT) {
                    const int b = m >> 11, tok = m & (Nn - 1);
                    const int h = n >> 6, cc = n & 63;
                    *reinterpret_cast<float2*>(
                        C + ((size_t)((b * Hh + h) * Nn + tok)) * HDc + cc) = o;
                } else {
                    *reinterpret_cast<float2*>(C + (size_t)m * DIMd + n) = o;
                }
            }
        }
    }
}

__global__ __launch_bounds__(256) void qkv_proj(
    const float* aq, const float* ak, const float* av,
    const float* wq, const float* wk, const float* wv,
    const float* bq, const float* bk, const float* bv,
    float* cq, float* ck, float* cv)
{
    extern __shared__ float smf[];
    const int z = blockIdx.z;
    const float* A = (z == 0) ? aq : (z == 1) ? ak : av;
    const float* W = (z == 0) ? wq : (z == 1) ? wk : wv;
    const float* b = (z == 0) ? bq : (z == 1) ? bk : bv;
    float*       C = (z == 0) ? cq : (z == 1) ? ck : cv;
    const float scale = (z == 0) ? ATTN_SCALE : 1.0f;
    proj_body<false, true, true>(A, W, b, C, scale, smf);
}

__global__ __launch_bounds__(256) void o_proj(
    const float* A, const float* W, const float* b, float* C)
{
    extern __shared__ float smf[];
    proj_body<true, false, false>(A, W, b, C, 1.0f, smf);
}

// ---------------------------------------------------------------------------
// Causal flash attention: 128 q-rows/CTA, 256 threads (8 warps, each owns a
// 16x64 strip). Register softmax. K/V 64-row tiles, cp.async double-buffered
// with TRUE overlap: issue kt+1 -> wait<1> (tile kt only) -> compute; tail
// barrier makes next-iteration buffer reuse WAR-safe. Heavy tiles first.
// ---------------------------------------------------------------------------
constexpr int AST = 68;  // smem row stride (words)
constexpr int ATT_SMEM = (4 * 64 + 128) * AST * 4;  // 2K + 2V + P = 104448 B

__global__ __launch_bounds__(256, 2) void attn2(
    const float* __restrict__ Qg, const float* __restrict__ Kg,
    const float* __restrict__ Vg, float* __restrict__ Og)
{
    extern __shared__ float smf[];
    const uint32_t su = (uint32_t)__cvta_generic_to_shared(smf);
    const uint32_t ksu[2] = {su, su + 64 * AST * 4};
    const uint32_t vsu[2] = {su + 2 * 64 * AST * 4, su + 3 * 64 * AST * 4};
    const uint32_t* Ksb[2] = {(const uint32_t*)smf,
                              (const uint32_t*)smf + 64 * AST};
    const uint32_t* Vsb[2] = {(const uint32_t*)smf + 2 * 64 * AST,
                              (const uint32_t*)smf + 3 * 64 * AST};
    uint32_t* Psu = (uint32_t*)smf + 4 * 64 * AST;

    const int bh = blockIdx.y;
    const int qtile = (gridDim.x - 1) - blockIdx.x;  // heavy-first
    const int q0 = qtile * 128;
    const size_t base = (size_t)bh * Nn * HDc;

    const int tid = threadIdx.x;
    const int w = tid >> 5, lane = tid & 31;
    const int gid = lane >> 2, tig = lane & 3;
    const int mrow = w * 16;

    auto issueKV = [&](int t_kt, int buf) {
        const float* Kb = Kg + base + (size_t)(t_kt * 64) * HDc;
        const float* Vb = Vg + base + (size_t)(t_kt * 64) * HDc;
#pragma unroll
        for (int t = 0; t < 4; t++) {
            const int idx = tid + t * 256;
            const int r = idx >> 4, cc = (idx & 15) << 2;
            cp16(ksu[buf] + (r * AST + cc) * 4, Kb + r * HDc + cc);
            cp16(vsu[buf] + (r * AST + cc) * 4, Vb + r * HDc + cc);
        }
        cp_commit();
    };

    // Q fragments: rows q0+mrow+gid, +8; all 64 head cols (tf32 bits in gmem)
    uint32_t qf[8][4];
    {
        const uint32_t* Qu = (const uint32_t*)(Qg + base) +
                             (size_t)(q0 + mrow + gid) * HDc;
#pragma unroll
        for (int s = 0; s < 8; s++) {
            const int kc = s * 8 + tig;
            qf[s][0] = Qu[kc];
            qf[s][1] = Qu[8 * HDc + kc];
            qf[s][2] = Qu[kc + 4];
            qf[s][3] = Qu[8 * HDc + kc + 4];
        }
    }

    float o[8][4];
#pragma unroll
    for (int ni = 0; ni < 8; ni++)
#pragma unroll
        for (int u = 0; u < 4; u++) o[ni][u] = 0.f;
    float m0r = -1e30f, m1r = -1e30f, l0 = 0.f, l1 = 0.f;

    const int ktmax = 2 * qtile + 1;
    issueKV(0, 0);

    for (int kt = 0; kt <= ktmax; kt++) {
        const int cur = kt & 1;
        // Prefetch next tile into the other buffer (WAR-safe thanks to the
        // barrier at the end of the previous iteration), then wait only for
        // tile kt so the prefetch overlaps this iteration's compute.
        if (kt < ktmax) { issueKV(kt + 1, cur ^ 1); cp_wait<1>(); }
        else            { cp_wait<0>(); }
        __syncthreads();

        // ---- S = Q K^T (16x64 per warp) ----
        float s4[8][4];
#pragma unroll
        for (int ni = 0; ni < 8; ni++)
#pragma unroll
            for (int u = 0; u < 4; u++) s4[ni][u] = 0.f;

        const uint32_t* Kb = Ksb[cur];
#pragma unroll
        for (int s = 0; s < 8; s++) {
            const int kk = s * 8;
            uint32_t bf[8][2];
#pragma unroll
            for (int ni = 0; ni < 8; ni++) {
                const uint32_t* p = Kb + (ni * 8 + gid) * AST + kk + tig;
                bf[ni][0] = p[0];
                bf[ni][1] = p[4];
            }
#pragma unroll
            for (int ni = 0; ni < 8; ni++)
                mma8(s4[ni], qf[s], bf[ni]);
        }

        // ---- causal mask (last two tiles only) ----
        if (kt >= 2 * qtile) {
            const int r0 = q0 + mrow + gid, r1 = r0 + 8;
            const int k0 = kt * 64;
#pragma unroll
            for (int ni = 0; ni < 8; ni++) {
                const int cc = k0 + ni * 8 + 2 * tig;
                if (cc > r0)     s4[ni][0] = -1e30f;
                if (cc + 1 > r0) s4[ni][1] = -1e30f;
                if (cc > r1)     s4[ni][2] = -1e30f;
                if (cc + 1 > r1) s4[ni][3] = -1e30f;
            }
        }

        // ---- register softmax (rows warp-local; quad reduction) ----
        float mx0 = -1e30f, mx1 = -1e30f;
#pragma unroll
        for (int ni = 0; ni < 8; ni++) {
            mx0 = fmaxf(mx0, fmaxf(s4[ni][0], s4[ni][1]));
            mx1 = fmaxf(mx1, fmaxf(s4[ni][2], s4[ni][3]));
        }
        mx0 = fmaxf(mx0, __shfl_xor_sync(0xffffffffu, mx0, 1));
        mx0 = fmaxf(mx0, __shfl_xor_sync(0xffffffffu, mx0, 2));
        mx1 = fmaxf(mx1, __shfl_xor_sync(0xffffffffu, mx1, 1));
        mx1 = fmaxf(mx1, __shfl_xor_sync(0xffffffffu, mx1, 2));
        const float mn0 = fmaxf(m0r, mx0);
        const float mn1 = fmaxf(m1r, mx1);
        const float f0 = __expf(m0r - mn0);
        const float f1 = __expf(m1r - mn1);
        m0r = mn0; m1r = mn1;

        float sum0 = 0.f, sum1 = 0.f;
        uint32_t* Pw = Psu + (mrow + gid) * AST + 2 * tig;
#pragma unroll
        for (int ni = 0; ni < 8; ni++) {
            const float e0 = __expf(s4[ni][0] - mn0);
            const float e1 = __expf(s4[ni][1] - mn0);
            const float e2 = __expf(s4[ni][2] - mn1);
            const float e3 = __expf(s4[ni][3] - mn1);
            sum0 += e0 + e1;
            sum1 += e2 + e3;
            uint2 pa, pb;
            pa.x = tf32r(e0); pa.y = tf32r(e1);
            pb.x = tf32r(e2); pb.y = tf32r(e3);
            *reinterpret_cast<uint2*>(Pw + ni * 8) = pa;
            *reinterpret_cast<uint2*>(Pw + 8 * AST + ni * 8) = pb;
        }
        sum0 += __shfl_xor_sync(0xffffffffu, sum0, 1);
        sum0 += __shfl_xor_sync(0xffffffffu, sum0, 2);
        sum1 += __shfl_xor_sync(0xffffffffu, sum1, 1);
        sum1 += __shfl_xor_sync(0xffffffffu, sum1, 2);
        l0 = l0 * f0 + sum0;
        l1 = l1 * f1 + sum1;

#pragma unroll
        for (int ni = 0; ni < 8; ni++) {
            o[ni][0] *= f0; o[ni][1] *= f0;
            o[ni][2] *= f1; o[ni][3] *= f1;
        }
        __syncwarp();

        // ---- O += P * V ----
        const uint32_t* Vb = Vsb[cur];
#pragma unroll
        for (int s = 0; s < 8; s++) {
            const int kk = s * 8;
            uint32_t af[4];
            const uint32_t* p = Psu + (mrow + gid) * AST + kk + tig;
            af[0] = p[0];
            af[1] = p[8 * AST];
            af[2] = p[4];
            af[3] = p[8 * AST + 4];
            uint32_t bf[8][2];
#pragma unroll
            for (int ni = 0; ni < 8; ni++) {
                const uint32_t* q = Vb + (kk + tig) * AST + ni * 8 + gid;
                bf[ni][0] = q[0];
                bf[ni][1] = q[4 * AST];
            }
#pragma unroll
            for (int ni = 0; ni < 8; ni++)
                mma8(o[ni], af, bf[ni]);
        }
        __syncthreads();   // all warps done with buf cur -> next issue WAR-safe
    }

    // ---- finalize: divide by l, tf32-round (feeds O-proj), store ----
    {
        const float inv0 = 1.f / l0;
        const float inv1 = 1.f / l1;
        const int r0 = q0 + mrow + gid;
        uint32_t* Ou = (uint32_t*)(Og + base);
#pragma unroll
        for (int ni = 0; ni < 8; ni++) {
            const int cc = ni * 8 + 2 * tig;
            uint2 oa, ob;
            oa.x = tf32r(o[ni][0] * inv0);
            oa.y = tf32r(o[ni][1] * inv0);
            ob.x = tf32r(o[ni][2] * inv1);
            ob.y = tf32r(o[ni][3] * inv1);
            *reinterpret_cast<uint2*>(Ou + (size_t)r0 * HDc + cc) = oa;
            *reinterpret_cast<uint2*>(Ou + (size_t)(r0 + 8) * HDc + cc) = ob;
        }
    }
}

// ---------------------------------------------------------------------------
extern "C" void kernel_launch(void* const* d_in, const int* in_sizes, int n_in,
                              void* d_out, int out_size)
{
    const float* q  = (const float*)d_in[0];
    const float* k  = (const float*)d_in[1];
    const float* v  = (const float*)d_in[2];
    // d_in[3] = mask (tril; causality applied analytically)
    const float* Wq = (const float*)d_in[4];
    const float* bq = (const float*)d_in[5];
    const float* Wk = (const float*)d_in[6];
    const float* bk = (const float*)d_in[7];
    const float* Wv = (const float*)d_in[8];
    const float* bv = (const float*)d_in[9];
    const float* Wo = (const float*)d_in[10];
    const float* bo = (const float*)d_in[11];
    float* out = (float*)d_out;

    float *qh, *kh, *vh, *ao, *qt, *kt, *vt, *wq, *wk, *wv, *wo;
    cudaGetSymbolAddress((void**)&qh, g_qh);
    cudaGetSymbolAddress((void**)&kh, g_kh);
    cudaGetSymbolAddress((void**)&vh, g_vh);
    cudaGetSymbolAddress((void**)&ao, g_ao);
    cudaGetSymbolAddress((void**)&qt, g_qt);
    cudaGetSymbolAddress((void**)&kt, g_kt);
    cudaGetSymbolAddress((void**)&vt, g_vt);
    cudaGetSymbolAddress((void**)&wq, g_wq);
    cudaGetSymbolAddress((void**)&wk, g_wk);
    cudaGetSymbolAddress((void**)&wv, g_wv);
    cudaGetSymbolAddress((void**)&wo, g_wo);

    static int cfg = 0;
    if (!cfg) {
        cudaFuncSetAttribute(qkv_proj,
            cudaFuncAttributeMaxDynamicSharedMemorySize, PROJ_SMEM);
        cudaFuncSetAttribute(o_proj,
            cudaFuncAttributeMaxDynamicSharedMemorySize, PROJ_SMEM);
        cudaFuncSetAttribute(attn2,
            cudaFuncAttributeMaxDynamicSharedMemorySize, ATT_SMEM);
        cfg = 1;
    }

    // Pre-round inputs and weights to tf32 (RNA) — one fused launch
    const int blocks_x = (Mrows * DIMd / 4 + 255) / 256;  // 4096 (covers both sizes)
    cvt_all<<<dim3(blocks_x, 1, 7), 256>>>(
        (const float4*)q, (const float4*)k, (const float4*)v,
        (const float4*)Wq, (const float4*)Wk, (const float4*)Wv, (const float4*)Wo,
        (float4*)qt, (float4*)kt, (float4*)vt,
        (float4*)wq, (float4*)wk, (float4*)wv, (float4*)wo);

    // Fused QKV projections (Q pre-scaled by ATTN_SCALE in epilogue)
    qkv_proj<<<dim3(DIMd / 128, Mrows / 128, 3), 256, PROJ_SMEM>>>(
        qt, kt, vt, wq, wk, wv, bq, bk, bv, qh, kh, vh);

    // Attention: 128 q-rows per CTA, heavy tiles first
    attn2<<<dim3(Nn / 128, Bb * Hh), 256, ATT_SMEM>>>(qh, kh, vh, ao);

    // Output projection
    o_proj<<<dim3(DIMd / 128, Mrows / 128), 256, PROJ_SMEM>>>(ao, wo, bo, out);
}

// round 7
// speedup vs baseline: 1.0916x; 1.0574x over previous
#include <cuda_runtime.h>
#include <math.h>
#include <stdint.h>

constexpr int Bb   = 2;
constexpr int Hh   = 16;
constexpr int Nn   = 2048;
constexpr int HDc  = 64;
constexpr int DIMd = 1024;
constexpr int Mrows = Bb * Nn;       // 4096
constexpr float ATTN_SCALE = 0.125f;

// Scratch buffers
__device__ float g_qh[Bb * Hh * Nn * HDc];   // Q heads (tf32 bits, pre-scaled)
__device__ float g_kh[Bb * Hh * Nn * HDc];   // K heads (tf32 bits)
__device__ float g_vh[Bb * Hh * Nn * HDc];   // V heads (tf32 bits)
__device__ float g_ao[Bb * Hh * Nn * HDc];   // attn out (tf32 bits)
__device__ float g_qt[Mrows * DIMd];         // tf32 copies of inputs
__device__ float g_kt[Mrows * DIMd];
__device__ float g_vt[Mrows * DIMd];
__device__ float g_wq[DIMd * DIMd];          // tf32 copies of weights
__device__ float g_wk[DIMd * DIMd];
__device__ float g_wv[DIMd * DIMd];
__device__ float g_wo[DIMd * DIMd];

__device__ __forceinline__ uint32_t tf32r(float x) {
    uint32_t y;
    asm("cvt.rna.tf32.f32 %0, %1;" : "=r"(y) : "f"(x));
    return y;
}

__device__ __forceinline__ void mma8(float* d, const uint32_t* a, const uint32_t* b) {
    asm volatile(
        "mma.sync.aligned.m16n8k8.row.col.f32.tf32.tf32.f32 "
        "{%0,%1,%2,%3}, {%4,%5,%6,%7}, {%8,%9}, {%0,%1,%2,%3};\n"
        : "+f"(d[0]), "+f"(d[1]), "+f"(d[2]), "+f"(d[3])
        : "r"(a[0]), "r"(a[1]), "r"(a[2]), "r"(a[3]), "r"(b[0]), "r"(b[1]));
}

__device__ __forceinline__ void cp16(uint32_t daddr, const void* src) {
    asm volatile("cp.async.cg.shared.global [%0], [%1], 16;\n"
                 :: "r"(daddr), "l"(src));
}
__device__ __forceinline__ void cp_commit() {
    asm volatile("cp.async.commit_group;\n");
}
template <int N>
__device__ __forceinline__ void cp_wait() {
    asm volatile("cp.async.wait_group %0;\n" :: "n"(N));
}

// ---------------------------------------------------------------------------
// Fused tf32 (RNA) pre-conversion for all 7 tensors (one launch).
// ---------------------------------------------------------------------------
__global__ __launch_bounds__(256) void cvt_all(
    const float4* q, const float4* k, const float4* v,
    const float4* wq, const float4* wk, const float4* wv, const float4* wo,
    float4* qt, float4* kt, float4* vt,
    float4* dwq, float4* dwk, float4* dwv, float4* dwo)
{
    const int z = blockIdx.z;
    const int n4 = (z < 3) ? (Mrows * DIMd / 4) : (DIMd * DIMd / 4);
    const int i = blockIdx.x * 256 + threadIdx.x;
    if (i >= n4) return;
    const float4* s;
    float4* d;
    switch (z) {
        case 0: s = q;  d = qt;  break;
        case 1: s = k;  d = kt;  break;
        case 2: s = v;  d = vt;  break;
        case 3: s = wq; d = dwq; break;
        case 4: s = wk; d = dwk; break;
        case 5: s = wv; d = dwv; break;
        default: s = wo; d = dwo; break;
    }
    float4 x = s[i];
    float4 o;
    o.x = __uint_as_float(tf32r(x.x));
    o.y = __uint_as_float(tf32r(x.y));
    o.z = __uint_as_float(tf32r(x.z));
    o.w = __uint_as_float(tf32r(x.w));
    d[i] = o;
}

// ---------------------------------------------------------------------------
// Projection GEMM (R3 proven config): 128x128x32 tiles, 2-stage cp.async
// double buffer, 73.7KB smem -> 2 CTAs/SM. 256 threads, 8 warps (2x4),
// 64x32 per warp, 4x4 m16n8k8 tiles.
// ---------------------------------------------------------------------------
constexpr int SKA = 36;                        // smem k-stride words
constexpr int PROJ_SMEM = 4 * 128 * SKA * 4;   // 73728 B

template <bool SPLIT_IN, bool SPLIT_OUT, bool ROUND>
__device__ __forceinline__ void proj_body(
    const float* __restrict__ A, const float* __restrict__ W,
    const float* __restrict__ bias, float* __restrict__ C, float scale,
    float* smf)
{
    const int m0 = blockIdx.y * 128, n0 = blockIdx.x * 128;
    const int tid = threadIdx.x;
    const int w = tid >> 5, lane = tid & 31;
    const int gid = lane >> 2, tig = lane & 3;
    const int mbase = (w & 1) * 64;
    const int nbase = (w >> 1) * 32;

    const uint32_t* Asb[2] = {(const uint32_t*)smf,
                              (const uint32_t*)smf + 128 * SKA};
    const uint32_t* Wsb[2] = {(const uint32_t*)smf + 2 * 128 * SKA,
                              (const uint32_t*)smf + 3 * 128 * SKA};
    const uint32_t su = (uint32_t)__cvta_generic_to_shared(smf);
    const uint32_t asu[2] = {su, su + 128 * SKA * 4};
    const uint32_t wsu[2] = {su + 2 * 128 * SKA * 4, su + 3 * 128 * SKA * 4};

    auto load_tiles = [&](int kt, int buf) {
        const int k0 = kt * 32;
#pragma unroll
        for (int t = 0; t < 4; t++) {
            const int idx = tid + t * 256;
            const int r = idx >> 3, c = (idx & 7) << 2;
            const float* ap;
            if (SPLIT_IN) {
                const int gm = m0 + r, gk = k0 + c;
                const int b = gm >> 11, tok = gm & (Nn - 1);
                const int h = gk >> 6, cc = gk & 63;
                ap = A + ((size_t)((b * Hh + h) * Nn + tok)) * HDc + cc;
            } else {
                ap = A + (size_t)(m0 + r) * DIMd + k0 + c;
            }
            cp16(asu[buf] + (r * SKA + c) * 4, ap);
            cp16(wsu[buf] + (r * SKA + c) * 4,
                 W + (size_t)(n0 + r) * DIMd + k0 + c);
        }
        cp_commit();
    };

    float c[4][4][4];
#pragma unroll
    for (int mi = 0; mi < 4; mi++)
#pragma unroll
        for (int ni = 0; ni < 4; ni++)
#pragma unroll
            for (int u = 0; u < 4; u++) c[mi][ni][u] = 0.f;

    load_tiles(0, 0);
    constexpr int ITERS = DIMd / 32;  // 32
    for (int kt = 0; kt < ITERS; kt++) {
        const int cur = kt & 1;
        if (kt + 1 < ITERS) { load_tiles(kt + 1, cur ^ 1); cp_wait<1>(); }
        else                { cp_wait<0>(); }
        __syncthreads();

        const uint32_t* Ab = Asb[cur];
        const uint32_t* Wb = Wsb[cur];
#pragma unroll
        for (int kk = 0; kk < 32; kk += 8) {
            uint32_t af[4][4];
#pragma unroll
            for (int mi = 0; mi < 4; mi++) {
                const uint32_t* p = Ab + (mbase + mi * 16 + gid) * SKA + kk + tig;
                af[mi][0] = p[0];
                af[mi][1] = p[8 * SKA];
                af[mi][2] = p[4];
                af[mi][3] = p[8 * SKA + 4];
            }
            uint32_t bf[4][2];
#pragma unroll
            for (int ni = 0; ni < 4; ni++) {
                const uint32_t* p = Wb + (nbase + ni * 8 + gid) * SKA + kk + tig;
                bf[ni][0] = p[0];
                bf[ni][1] = p[4];
            }
#pragma unroll
            for (int mi = 0; mi < 4; mi++)
#pragma unroll
                for (int ni = 0; ni < 4; ni++)
                    mma8(c[mi][ni], af[mi], bf[ni]);
        }
        __syncthreads();
    }

    // Epilogue
#pragma unroll
    for (int mi = 0; mi < 4; mi++) {
#pragma unroll
        for (int ni = 0; ni < 4; ni++) {
            const int n = n0 + nbase + ni * 8 + 2 * tig;
            const float bx = bias[n], by = bias[n + 1];
#pragma unroll
            for (int hr = 0; hr < 2; hr++) {
                const int m = m0 + mbase + mi * 16 + gid + hr * 8;
                float2 o;
                o.x = (c[mi][ni][hr * 2 + 0] + bx) * scale;
                o.y = (c[mi][ni][hr * 2 + 1] + by) * scale;
                if (ROUND) {
                    o.x = __uint_as_float(tf32r(o.x));
                    o.y = __uint_as_float(tf32r(o.y));
                }
                if (SPLIT_OUT) {
                    const int b = m >> 11, tok = m & (Nn - 1);
                    const int h = n >> 6, cc = n & 63;
                    *reinterpret_cast<float2*>(
                        C + ((size_t)((b * Hh + h) * Nn + tok)) * HDc + cc) = o;
                } else {
                    *reinterpret_cast<float2*>(C + (size_t)m * DIMd + n) = o;
                }
            }
        }
    }
}

__global__ __launch_bounds__(256) void qkv_proj(
    const float* aq, const float* ak, const float* av,
    const float* wq, const float* wk, const float* wv,
    const float* bq, const float* bk, const float* bv,
    float* cq, float* ck, float* cv)
{
    extern __shared__ float smf[];
    const int z = blockIdx.z;
    const float* A = (z == 0) ? aq : (z == 1) ? ak : av;
    const float* W = (z == 0) ? wq : (z == 1) ? wk : wv;
    const float* b = (z == 0) ? bq : (z == 1) ? bk : bv;
    float*       C = (z == 0) ? cq : (z == 1) ? ck : cv;
    const float scale = (z == 0) ? ATTN_SCALE : 1.0f;
    proj_body<false, true, true>(A, W, b, C, scale, smf);
}

__global__ __launch_bounds__(256) void o_proj(
    const float* A, const float* W, const float* b, float* C)
{
    extern __shared__ float smf[];
    proj_body<true, false, false>(A, W, b, C, 1.0f, smf);
}

// ---------------------------------------------------------------------------
// Causal flash attention (R3 proven config + heavy-first): 64 q-rows/CTA,
// 128 threads (4 warps, each owns a 16x64 strip). Register softmax. K/V
// 64-row tiles, cp.async double-buffered with true overlap.
// ---------------------------------------------------------------------------
constexpr int AST = 68;  // smem row stride (words)
constexpr int ATT_SMEM = 5 * 64 * AST * 4;  // 2xK, 2xV, P = 87040 B

__global__ __launch_bounds__(128) void attn2(
    const float* __restrict__ Qg, const float* __restrict__ Kg,
    const float* __restrict__ Vg, float* __restrict__ Og)
{
    extern __shared__ float smf[];
    const uint32_t su = (uint32_t)__cvta_generic_to_shared(smf);
    const uint32_t ksu[2] = {su, su + 64 * AST * 4};
    const uint32_t vsu[2] = {su + 2 * 64 * AST * 4, su + 3 * 64 * AST * 4};
    const uint32_t* Ksb[2] = {(const uint32_t*)smf,
                              (const uint32_t*)smf + 64 * AST};
    const uint32_t* Vsb[2] = {(const uint32_t*)smf + 2 * 64 * AST,
                              (const uint32_t*)smf + 3 * 64 * AST};
    uint32_t* Psu = (uint32_t*)smf + 4 * 64 * AST;

    const int bh = blockIdx.y;
    const int qt = (gridDim.x - 1) - blockIdx.x;   // heavy-first
    const int q0 = qt * 64;
    const size_t base = (size_t)bh * Nn * HDc;

    const int tid = threadIdx.x;
    const int w = tid >> 5, lane = tid & 31;
    const int gid = lane >> 2, tig = lane & 3;
    const int mrow = w * 16;

    auto issueKV = [&](int t_kt, int buf) {
        const float* Kb = Kg + base + (size_t)(t_kt * 64) * HDc;
        const float* Vb = Vg + base + (size_t)(t_kt * 64) * HDc;
#pragma unroll
        for (int t = 0; t < 8; t++) {
            const int idx = tid + t * 128;
            const int r = idx >> 4, cc = (idx & 15) << 2;
            cp16(ksu[buf] + (r * AST + cc) * 4, Kb + r * HDc + cc);
            cp16(vsu[buf] + (r * AST + cc) * 4, Vb + r * HDc + cc);
        }
        cp_commit();
    };

    // Q fragments: warp rows mrow+gid, mrow+gid+8; all 64 hd cols
    uint32_t qf[8][4];
    {
        const uint32_t* Qu = (const uint32_t*)(Qg + base) +
                             (size_t)(q0 + mrow + gid) * HDc;
#pragma unroll
        for (int s = 0; s < 8; s++) {
            const int kc = s * 8 + tig;
            qf[s][0] = Qu[kc];
            qf[s][1] = Qu[8 * HDc + kc];
            qf[s][2] = Qu[kc + 4];
            qf[s][3] = Qu[8 * HDc + kc + 4];
        }
    }

    float o[8][4];
#pragma unroll
    for (int ni = 0; ni < 8; ni++)
#pragma unroll
        for (int u = 0; u < 4; u++) o[ni][u] = 0.f;
    float m0r = -1e30f, m1r = -1e30f, l0 = 0.f, l1 = 0.f;

    issueKV(0, 0);

    for (int kt = 0; kt <= qt; kt++) {
        const int cur = kt & 1;
        if (kt < qt) { issueKV(kt + 1, cur ^ 1); cp_wait<1>(); }
        else         { cp_wait<0>(); }
        __syncthreads();

        // ---- S = Q K^T (16x64 per warp) ----
        float s4[8][4];
#pragma unroll
        for (int ni = 0; ni < 8; ni++)
#pragma unroll
            for (int u = 0; u < 4; u++) s4[ni][u] = 0.f;

        const uint32_t* Kb = Ksb[cur];
#pragma unroll
        for (int s = 0; s < 8; s++) {
            const int kk = s * 8;
            uint32_t bf[8][2];
#pragma unroll
            for (int ni = 0; ni < 8; ni++) {
                const uint32_t* p = Kb + (ni * 8 + gid) * AST + kk + tig;
                bf[ni][0] = p[0];
                bf[ni][1] = p[4];
            }
#pragma unroll
            for (int ni = 0; ni < 8; ni++)
                mma8(s4[ni], qf[s], bf[ni]);
        }

        // ---- causal mask (diagonal tile only) ----
        if (kt == qt) {
            const int r0 = q0 + mrow + gid, r1 = r0 + 8;
            const int k0 = kt * 64;
#pragma unroll
            for (int ni = 0; ni < 8; ni++) {
                const int cc = k0 + ni * 8 + 2 * tig;
                if (cc > r0)     s4[ni][0] = -1e30f;
                if (cc + 1 > r0) s4[ni][1] = -1e30f;
                if (cc > r1)     s4[ni][2] = -1e30f;
                if (cc + 1 > r1) s4[ni][3] = -1e30f;
            }
        }

        // ---- register softmax (rows warp-local; quad reduction) ----
        float mx0 = -1e30f, mx1 = -1e30f;
#pragma unroll
        for (int ni = 0; ni < 8; ni++) {
            mx0 = fmaxf(mx0, fmaxf(s4[ni][0], s4[ni][1]));
            mx1 = fmaxf(mx1, fmaxf(s4[ni][2], s4[ni][3]));
        }
        mx0 = fmaxf(mx0, __shfl_xor_sync(0xffffffffu, mx0, 1));
        mx0 = fmaxf(mx0, __shfl_xor_sync(0xffffffffu, mx0, 2));
        mx1 = fmaxf(mx1, __shfl_xor_sync(0xffffffffu, mx1, 1));
        mx1 = fmaxf(mx1, __shfl_xor_sync(0xffffffffu, mx1, 2));
        const float mn0 = fmaxf(m0r, mx0);
        const float mn1 = fmaxf(m1r, mx1);
        const float f0 = __expf(m0r - mn0);
        const float f1 = __expf(m1r - mn1);
        m0r = mn0; m1r = mn1;

        float sum0 = 0.f, sum1 = 0.f;
        uint32_t* Pw = Psu + (mrow + gid) * AST + 2 * tig;
#pragma unroll
        for (int ni = 0; ni < 8; ni++) {
            const float e0 = __expf(s4[ni][0] - mn0);
            const float e1 = __expf(s4[ni][1] - mn0);
            const float e2 = __expf(s4[ni][2] - mn1);
            const float e3 = __expf(s4[ni][3] - mn1);
            sum0 += e0 + e1;
            sum1 += e2 + e3;
            uint2 pa, pb;
            pa.x = tf32r(e0); pa.y = tf32r(e1);
            pb.x = tf32r(e2); pb.y = tf32r(e3);
            *reinterpret_cast<uint2*>(Pw + ni * 8) = pa;
            *reinterpret_cast<uint2*>(Pw + 8 * AST + ni * 8) = pb;
        }
        sum0 += __shfl_xor_sync(0xffffffffu, sum0, 1);
        sum0 += __shfl_xor_sync(0xffffffffu, sum0, 2);
        sum1 += __shfl_xor_sync(0xffffffffu, sum1, 1);
        sum1 += __shfl_xor_sync(0xffffffffu, sum1, 2);
        l0 = l0 * f0 + sum0;
        l1 = l1 * f1 + sum1;

#pragma unroll
        for (int ni = 0; ni < 8; ni++) {
            o[ni][0] *= f0; o[ni][1] *= f0;
            o[ni][2] *= f1; o[ni][3] *= f1;
        }
        __syncwarp();

        // ---- O += P * V ----
        const uint32_t* Vb = Vsb[cur];
#pragma unroll
        for (int s = 0; s < 8; s++) {
            const int kk = s * 8;
            uint32_t af[4];
            const uint32_t* p = Psu + (mrow + gid) * AST + kk + tig;
            af[0] = p[0];
            af[1] = p[8 * AST];
            af[2] = p[4];
            af[3] = p[8 * AST + 4];
            uint32_t bf[8][2];
#pragma unroll
            for (int ni = 0; ni < 8; ni++) {
                const uint32_t* q = Vb + (kk + tig) * AST + ni * 8 + gid;
                bf[ni][0] = q[0];
                bf[ni][1] = q[4 * AST];
            }
#pragma unroll
            for (int ni = 0; ni < 8; ni++)
                mma8(o[ni], af, bf[ni]);
        }
        __syncthreads();
    }

    // ---- finalize: divide by l, tf32-round (feeds O-proj), store ----
    {
        const float inv0 = 1.f / l0;
        const float inv1 = 1.f / l1;
        const int r0 = q0 + mrow + gid;
        uint32_t* Ou = (uint32_t*)(Og + base);
#pragma unroll
        for (int ni = 0; ni < 8; ni++) {
            const int cc = ni * 8 + 2 * tig;
            uint2 oa, ob;
            oa.x = tf32r(o[ni][0] * inv0);
            oa.y = tf32r(o[ni][1] * inv0);
            ob.x = tf32r(o[ni][2] * inv1);
            ob.y = tf32r(o[ni][3] * inv1);
            *reinterpret_cast<uint2*>(Ou + (size_t)r0 * HDc + cc) = oa;
            *reinterpret_cast<uint2*>(Ou + (size_t)(r0 + 8) * HDc + cc) = ob;
        }
    }
}

// ---------------------------------------------------------------------------
extern "C" void kernel_launch(void* const* d_in, const int* in_sizes, int n_in,
                              void* d_out, int out_size)
{
    const float* q  = (const float*)d_in[0];
    const float* k  = (const float*)d_in[1];
    const float* v  = (const float*)d_in[2];
    // d_in[3] = mask (tril; causality applied analytically)
    const float* Wq = (const float*)d_in[4];
    const float* bq = (const float*)d_in[5];
    const float* Wk = (const float*)d_in[6];
    const float* bk = (const float*)d_in[7];
    const float* Wv = (const float*)d_in[8];
    const float* bv = (const float*)d_in[9];
    const float* Wo = (const float*)d_in[10];
    const float* bo = (const float*)d_in[11];
    float* out = (float*)d_out;

    float *qh, *kh, *vh, *ao, *qt, *kt, *vt, *wq, *wk, *wv, *wo;
    cudaGetSymbolAddress((void**)&qh, g_qh);
    cudaGetSymbolAddress((void**)&kh, g_kh);
    cudaGetSymbolAddress((void**)&vh, g_vh);
    cudaGetSymbolAddress((void**)&ao, g_ao);
    cudaGetSymbolAddress((void**)&qt, g_qt);
    cudaGetSymbolAddress((void**)&kt, g_kt);
    cudaGetSymbolAddress((void**)&vt, g_vt);
    cudaGetSymbolAddress((void**)&wq, g_wq);
    cudaGetSymbolAddress((void**)&wk, g_wk);
    cudaGetSymbolAddress((void**)&wv, g_wv);
    cudaGetSymbolAddress((void**)&wo, g_wo);

    static int cfg = 0;
    if (!cfg) {
        cudaFuncSetAttribute(qkv_proj,
            cudaFuncAttributeMaxDynamicSharedMemorySize, PROJ_SMEM);
        cudaFuncSetAttribute(o_proj,
            cudaFuncAttributeMaxDynamicSharedMemorySize, PROJ_SMEM);
        cudaFuncSetAttribute(attn2,
            cudaFuncAttributeMaxDynamicSharedMemorySize, ATT_SMEM);
        cfg = 1;
    }

    // Pre-round inputs and weights to tf32 (RNA) — one fused launch
    const int blocks_x = (Mrows * DIMd / 4 + 255) / 256;
    cvt_all<<<dim3(blocks_x, 1, 7), 256>>>(
        (const float4*)q, (const float4*)k, (const float4*)v,
        (const float4*)Wq, (const float4*)Wk, (const float4*)Wv, (const float4*)Wo,
        (float4*)qt, (float4*)kt, (float4*)vt,
        (float4*)wq, (float4*)wk, (float4*)wv, (float4*)wo);

    // Fused QKV projections (Q pre-scaled by ATTN_SCALE in epilogue)
    qkv_proj<<<dim3(DIMd / 128, Mrows / 128, 3), 256, PROJ_SMEM>>>(
        qt, kt, vt, wq, wk, wv, bq, bk, bv, qh, kh, vh);

    // Attention: 64 q-rows per CTA, heavy tiles first
    attn2<<<dim3(Nn / 64, Bb * Hh), 128, ATT_SMEM>>>(qh, kh, vh, ao);

    // Output projection
    o_proj<<<dim3(DIMd / 128, Mrows / 128), 256, PROJ_SMEM>>>(ao, wo, bo, out);
}

// round 8
// speedup vs baseline: 1.1460x; 1.0499x over previous
#include <cuda_runtime.h>
#include <math.h>
#include <stdint.h>

constexpr int Bb   = 2;
constexpr int Hh   = 16;
constexpr int Nn   = 2048;
constexpr int HDc  = 64;
constexpr int DIMd = 1024;
constexpr int Mrows = Bb * Nn;       // 4096
constexpr float ATTN_SCALE = 0.125f;

// k-group permutation: storage position 2t holds logical k t, 2t+1 holds t+4.
// Applied to every contraction dimension so mma fragments load as 64-bit pairs.

// Scratch buffers
__device__ float g_qh[Bb * Hh * Nn * HDc];   // Q heads (tf32, perm head dim, pre-scaled)
__device__ float g_kh[Bb * Hh * Nn * HDc];   // K heads (tf32, perm head dim)
__device__ float g_vh[Bb * Hh * Nn * HDc];   // V heads (tf32, perm head dim)
__device__ float g_ao[Bb * Hh * Nn * HDc];   // attn out (tf32, perm head dim)
__device__ float g_qt[Mrows * DIMd];         // tf32 perm-k copies of inputs
__device__ float g_kt[Mrows * DIMd];
__device__ float g_vt[Mrows * DIMd];
__device__ float g_wq[DIMd * DIMd];          // tf32 perm-k copies of weights
__device__ float g_wk[DIMd * DIMd];
__device__ float g_wv[DIMd * DIMd];
__device__ float g_wo[DIMd * DIMd];

__device__ __forceinline__ uint32_t tf32r(float x) {
    uint32_t y;
    asm("cvt.rna.tf32.f32 %0, %1;" : "=r"(y) : "f"(x));
    return y;
}

__device__ __forceinline__ void mma8(float* d, const uint32_t* a, const uint32_t* b) {
    asm volatile(
        "mma.sync.aligned.m16n8k8.row.col.f32.tf32.tf32.f32 "
        "{%0,%1,%2,%3}, {%4,%5,%6,%7}, {%8,%9}, {%0,%1,%2,%3};\n"
        : "+f"(d[0]), "+f"(d[1]), "+f"(d[2]), "+f"(d[3])
        : "r"(a[0]), "r"(a[1]), "r"(a[2]), "r"(a[3]), "r"(b[0]), "r"(b[1]));
}

__device__ __forceinline__ void cp16(uint32_t daddr, const void* src) {
    asm volatile("cp.async.cg.shared.global [%0], [%1], 16;\n"
                 :: "r"(daddr), "l"(src));
}
__device__ __forceinline__ void cp_commit() {
    asm volatile("cp.async.commit_group;\n");
}
template <int N>
__device__ __forceinline__ void cp_wait() {
    asm volatile("cp.async.wait_group %0;\n" :: "n"(N));
}

// ---------------------------------------------------------------------------
// Fused tf32 (RNA) conversion + k-group permute. Each thread handles one
// 8-wide k-group: out[0..7] = {in0,in4,in1,in5,in2,in6,in3,in7} (tf32).
// ---------------------------------------------------------------------------
__global__ __launch_bounds__(256) void cvt_all(
    const float4* q, const float4* k, const float4* v,
    const float4* wq, const float4* wk, const float4* wv, const float4* wo,
    float4* qt, float4* kt, float4* vt,
    float4* dwq, float4* dwk, float4* dwv, float4* dwo)
{
    const int z = blockIdx.z;
    const int n8 = (z < 3) ? (Mrows * DIMd / 8) : (DIMd * DIMd / 8);
    const int i = blockIdx.x * 256 + threadIdx.x;
    if (i >= n8) return;
    const float4* s;
    float4* d;
    switch (z) {
        case 0: s = q;  d = qt;  break;
        case 1: s = k;  d = kt;  break;
        case 2: s = v;  d = vt;  break;
        case 3: s = wq; d = dwq; break;
        case 4: s = wk; d = dwk; break;
        case 5: s = wv; d = dwv; break;
        default: s = wo; d = dwo; break;
    }
    const float4 a = s[2 * i];       // logical k 0..3
    const float4 b = s[2 * i + 1];   // logical k 4..7
    float4 o0, o1;
    o0.x = __uint_as_float(tf32r(a.x)); o0.y = __uint_as_float(tf32r(b.x));
    o0.z = __uint_as_float(tf32r(a.y)); o0.w = __uint_as_float(tf32r(b.y));
    o1.x = __uint_as_float(tf32r(a.z)); o1.y = __uint_as_float(tf32r(b.z));
    o1.z = __uint_as_float(tf32r(a.w)); o1.w = __uint_as_float(tf32r(b.w));
    d[2 * i]     = o0;
    d[2 * i + 1] = o1;
}

// ---------------------------------------------------------------------------
// Projection GEMM: 128x128x32 tiles, 2-stage cp.async double buffer,
// 81.9KB smem -> 2 CTAs/SM. 256 threads, 8 warps (2x4), 64x32 per warp.
// Operands perm-k in gmem -> all fragment loads are LDS.64 (conflict-free,
// SKA=40 ≡ 8 mod 32).
// ---------------------------------------------------------------------------
constexpr int SKA = 40;                        // smem k-stride words
constexpr int PROJ_SMEM = 4 * 128 * SKA * 4;   // 81920 B

template <bool SPLIT_IN, bool SPLIT_OUT, bool ROUND>
__device__ __forceinline__ void proj_body(
    const float* __restrict__ A, const float* __restrict__ W,
    const float* __restrict__ bias, float* __restrict__ C, float scale,
    float* smf)
{
    const int m0 = blockIdx.y * 128, n0 = blockIdx.x * 128;
    const int tid = threadIdx.x;
    const int w = tid >> 5, lane = tid & 31;
    const int gid = lane >> 2, tig = lane & 3;
    const int mbase = (w & 1) * 64;
    const int nbase = (w >> 1) * 32;

    const uint32_t* Asb[2] = {(const uint32_t*)smf,
                              (const uint32_t*)smf + 128 * SKA};
    const uint32_t* Wsb[2] = {(const uint32_t*)smf + 2 * 128 * SKA,
                              (const uint32_t*)smf + 3 * 128 * SKA};
    const uint32_t su = (uint32_t)__cvta_generic_to_shared(smf);
    const uint32_t asu[2] = {su, su + 128 * SKA * 4};
    const uint32_t wsu[2] = {su + 2 * 128 * SKA * 4, su + 3 * 128 * SKA * 4};

    auto load_tiles = [&](int kt, int buf) {
        const int k0 = kt * 32;
#pragma unroll
        for (int t = 0; t < 4; t++) {
            const int idx = tid + t * 256;
            const int r = idx >> 3, c = (idx & 7) << 2;
            const float* ap;
            if (SPLIT_IN) {
                const int gm = m0 + r, gk = k0 + c;
                const int b = gm >> 11, tok = gm & (Nn - 1);
                const int h = gk >> 6, cc = gk & 63;
                ap = A + ((size_t)((b * Hh + h) * Nn + tok)) * HDc + cc;
            } else {
                ap = A + (size_t)(m0 + r) * DIMd + k0 + c;
            }
            cp16(asu[buf] + (r * SKA + c) * 4, ap);
            cp16(wsu[buf] + (r * SKA + c) * 4,
                 W + (size_t)(n0 + r) * DIMd + k0 + c);
        }
        cp_commit();
    };

    float c[4][4][4];
#pragma unroll
    for (int mi = 0; mi < 4; mi++)
#pragma unroll
        for (int ni = 0; ni < 4; ni++)
#pragma unroll
            for (int u = 0; u < 4; u++) c[mi][ni][u] = 0.f;

    load_tiles(0, 0);
    constexpr int ITERS = DIMd / 32;  // 32
    for (int kt = 0; kt < ITERS; kt++) {
        const int cur = kt & 1;
        if (kt + 1 < ITERS) { load_tiles(kt + 1, cur ^ 1); cp_wait<1>(); }
        else                { cp_wait<0>(); }
        __syncthreads();

        const uint32_t* Ab = Asb[cur];
        const uint32_t* Wb = Wsb[cur];
#pragma unroll
        for (int kk = 0; kk < 32; kk += 8) {
            uint32_t af[4][4];
#pragma unroll
            for (int mi = 0; mi < 4; mi++) {
                const int row = mbase + mi * 16 + gid;
                const uint2 a0 = *reinterpret_cast<const uint2*>(
                    Ab + row * SKA + kk + 2 * tig);
                const uint2 a1 = *reinterpret_cast<const uint2*>(
                    Ab + (row + 8) * SKA + kk + 2 * tig);
                af[mi][0] = a0.x; af[mi][1] = a1.x;
                af[mi][2] = a0.y; af[mi][3] = a1.y;
            }
            uint32_t bf[4][2];
#pragma unroll
            for (int ni = 0; ni < 4; ni++) {
                const uint2 b = *reinterpret_cast<const uint2*>(
                    Wb + (nbase + ni * 8 + gid) * SKA + kk + 2 * tig);
                bf[ni][0] = b.x;
                bf[ni][1] = b.y;
            }
#pragma unroll
            for (int mi = 0; mi < 4; mi++)
#pragma unroll
                for (int ni = 0; ni < 4; ni++)
                    mma8(c[mi][ni], af[mi], bf[ni]);
        }
        __syncthreads();
    }

    // Epilogue. Logical cols c0=2tig, c1=2tig+1; permuted positions
    // p0 = {0,4,1,5}[tig], p1 = p0+2 (only used when SPLIT_OUT feeds attn).
    const int p0 = (tig < 2) ? 4 * tig : 4 * tig - 7;
#pragma unroll
    for (int mi = 0; mi < 4; mi++) {
#pragma unroll
        for (int ni = 0; ni < 4; ni++) {
            const int nlog = n0 + nbase + ni * 8 + 2 * tig;
            const float bx = bias[nlog], by = bias[nlog + 1];
#pragma unroll
            for (int hr = 0; hr < 2; hr++) {
                const int m = m0 + mbase + mi * 16 + gid + hr * 8;
                float ox = (c[mi][ni][hr * 2 + 0] + bx) * scale;
                float oy = (c[mi][ni][hr * 2 + 1] + by) * scale;
                if (ROUND) {
                    ox = __uint_as_float(tf32r(ox));
                    oy = __uint_as_float(tf32r(oy));
                }
                if (SPLIT_OUT) {
                    const int b = m >> 11, tok = m & (Nn - 1);
                    const int np0 = n0 + nbase + ni * 8 + p0;
                    const int h = np0 >> 6;
                    float* dst = C + ((size_t)((b * Hh + h) * Nn + tok)) * HDc;
                    dst[np0 & 63]       = ox;
                    dst[(np0 + 2) & 63] = oy;
                } else {
                    float2 o; o.x = ox; o.y = oy;
                    *reinterpret_cast<float2*>(C + (size_t)m * DIMd + nlog) = o;
                }
            }
        }
    }
}

__global__ __launch_bounds__(256) void qkv_proj(
    const float* aq, const float* ak, const float* av,
    const float* wq, const float* wk, const float* wv,
    const float* bq, const float* bk, const float* bv,
    float* cq, float* ck, float* cv)
{
    extern __shared__ float smf[];
    const int z = blockIdx.z;
    const float* A = (z == 0) ? aq : (z == 1) ? ak : av;
    const float* W = (z == 0) ? wq : (z == 1) ? wk : wv;
    const float* b = (z == 0) ? bq : (z == 1) ? bk : bv;
    float*       C = (z == 0) ? cq : (z == 1) ? ck : cv;
    const float scale = (z == 0) ? ATTN_SCALE : 1.0f;
    proj_body<false, true, true>(A, W, b, C, scale, smf);
}

__global__ __launch_bounds__(256) void o_proj(
    const float* A, const float* W, const float* b, float* C)
{
    extern __shared__ float smf[];
    proj_body<true, false, false>(A, W, b, C, 1.0f, smf);
}

// ---------------------------------------------------------------------------
// Causal flash attention: 64 q-rows/CTA, 128 threads (4 warps, 16x64 strips),
// register softmax, cp.async double buffer with true overlap, heavy-first.
// Head dim perm-k (LDS.64 K frags, LDG.64 Q frags); P stored perm-token
// (LDS.64 P frags). AST=72 ≡ 8 mod 32: conflict-free 64-bit loads and
// conflict-free V loads.
// ---------------------------------------------------------------------------
constexpr int AST = 72;  // smem row stride (words)
constexpr int ATT_SMEM = 5 * 64 * AST * 4;  // 2xK, 2xV, P = 92160 B

__global__ __launch_bounds__(128) void attn2(
    const float* __restrict__ Qg, const float* __restrict__ Kg,
    const float* __restrict__ Vg, float* __restrict__ Og)
{
    extern __shared__ float smf[];
    const uint32_t su = (uint32_t)__cvta_generic_to_shared(smf);
    const uint32_t ksu[2] = {su, su + 64 * AST * 4};
    const uint32_t vsu[2] = {su + 2 * 64 * AST * 4, su + 3 * 64 * AST * 4};
    const uint32_t* Ksb[2] = {(const uint32_t*)smf,
                              (const uint32_t*)smf + 64 * AST};
    const uint32_t* Vsb[2] = {(const uint32_t*)smf + 2 * 64 * AST,
                              (const uint32_t*)smf + 3 * 64 * AST};
    uint32_t* Psu = (uint32_t*)smf + 4 * 64 * AST;

    const int bh = blockIdx.y;
    const int qt = (gridDim.x - 1) - blockIdx.x;   // heavy-first
    const int q0 = qt * 64;
    const size_t base = (size_t)bh * Nn * HDc;

    const int tid = threadIdx.x;
    const int w = tid >> 5, lane = tid & 31;
    const int gid = lane >> 2, tig = lane & 3;
    const int mrow = w * 16;
    const int p0 = (tig < 2) ? 4 * tig : 4 * tig - 7;  // perm pos of col 2tig

    auto issueKV = [&](int t_kt, int buf) {
        const float* Kb = Kg + base + (size_t)(t_kt * 64) * HDc;
        const float* Vb = Vg + base + (size_t)(t_kt * 64) * HDc;
#pragma unroll
        for (int t = 0; t < 8; t++) {
            const int idx = tid + t * 128;
            const int r = idx >> 4, cc = (idx & 15) << 2;
            cp16(ksu[buf] + (r * AST + cc) * 4, Kb + r * HDc + cc);
            cp16(vsu[buf] + (r * AST + cc) * 4, Vb + r * HDc + cc);
        }
        cp_commit();
    };

    // Q fragments from perm-k qh: 64-bit pairs at 2tig
    uint32_t qf[8][4];
    {
        const uint32_t* Qu = (const uint32_t*)(Qg + base) +
                             (size_t)(q0 + mrow + gid) * HDc;
#pragma unroll
        for (int s = 0; s < 8; s++) {
            const uint2 u0 = *reinterpret_cast<const uint2*>(Qu + s * 8 + 2 * tig);
            const uint2 u1 = *reinterpret_cast<const uint2*>(Qu + 8 * HDc + s * 8 + 2 * tig);
            qf[s][0] = u0.x; qf[s][1] = u1.x;
            qf[s][2] = u0.y; qf[s][3] = u1.y;
        }
    }

    float o[8][4];
#pragma unroll
    for (int ni = 0; ni < 8; ni++)
#pragma unroll
        for (int u = 0; u < 4; u++) o[ni][u] = 0.f;
    float m0r = -1e30f, m1r = -1e30f, l0 = 0.f, l1 = 0.f;

    issueKV(0, 0);

    for (int kt = 0; kt <= qt; kt++) {
        const int cur = kt & 1;
        if (kt < qt) { issueKV(kt + 1, cur ^ 1); cp_wait<1>(); }
        else         { cp_wait<0>(); }
        __syncthreads();

        // ---- S = Q K^T (16x64 per warp); K head dim perm -> LDS.64 ----
        float s4[8][4];
#pragma unroll
        for (int ni = 0; ni < 8; ni++)
#pragma unroll
            for (int u = 0; u < 4; u++) s4[ni][u] = 0.f;

        const uint32_t* Kb = Ksb[cur];
#pragma unroll
        for (int s = 0; s < 8; s++) {
            const int kk = s * 8;
            uint32_t bf[8][2];
#pragma unroll
            for (int ni = 0; ni < 8; ni++) {
                const uint2 b = *reinterpret_cast<const uint2*>(
                    Kb + (ni * 8 + gid) * AST + kk + 2 * tig);
                bf[ni][0] = b.x;
                bf[ni][1] = b.y;
            }
#pragma unroll
            for (int ni = 0; ni < 8; ni++)
                mma8(s4[ni], qf[s], bf[ni]);
        }

        // ---- causal mask (diagonal tile only; token cols are logical) ----
        if (kt == qt) {
            const int r0 = q0 + mrow + gid, r1 = r0 + 8;
            const int k0 = kt * 64;
#pragma unroll
            for (int ni = 0; ni < 8; ni++) {
                const int cc = k0 + ni * 8 + 2 * tig;
                if (cc > r0)     s4[ni][0] = -1e30f;
                if (cc + 1 > r0) s4[ni][1] = -1e30f;
                if (cc > r1)     s4[ni][2] = -1e30f;
                if (cc + 1 > r1) s4[ni][3] = -1e30f;
            }
        }

        // ---- register softmax ----
        float mx0 = -1e30f, mx1 = -1e30f;
#pragma unroll
        for (int ni = 0; ni < 8; ni++) {
            mx0 = fmaxf(mx0, fmaxf(s4[ni][0], s4[ni][1]));
            mx1 = fmaxf(mx1, fmaxf(s4[ni][2], s4[ni][3]));
        }
        mx0 = fmaxf(mx0, __shfl_xor_sync(0xffffffffu, mx0, 1));
        mx0 = fmaxf(mx0, __shfl_xor_sync(0xffffffffu, mx0, 2));
        mx1 = fmaxf(mx1, __shfl_xor_sync(0xffffffffu, mx1, 1));
        mx1 = fmaxf(mx1, __shfl_xor_sync(0xffffffffu, mx1, 2));
        const float mn0 = fmaxf(m0r, mx0);
        const float mn1 = fmaxf(m1r, mx1);
        const float f0 = __expf(m0r - mn0);
        const float f1 = __expf(m1r - mn1);
        m0r = mn0; m1r = mn1;

        // P written with perm-token positions: col 2tig -> p0, 2tig+1 -> p0+2
        float sum0 = 0.f, sum1 = 0.f;
        uint32_t* PwA = Psu + (mrow + gid) * AST;
        uint32_t* PwB = PwA + 8 * AST;
#pragma unroll
        for (int ni = 0; ni < 8; ni++) {
            const float e0 = __expf(s4[ni][0] - mn0);
            const float e1 = __expf(s4[ni][1] - mn0);
            const float e2 = __expf(s4[ni][2] - mn1);
            const float e3 = __expf(s4[ni][3] - mn1);
            sum0 += e0 + e1;
            sum1 += e2 + e3;
            PwA[ni * 8 + p0]     = tf32r(e0);
            PwA[ni * 8 + p0 + 2] = tf32r(e1);
            PwB[ni * 8 + p0]     = tf32r(e2);
            PwB[ni * 8 + p0 + 2] = tf32r(e3);
        }
        sum0 += __shfl_xor_sync(0xffffffffu, sum0, 1);
        sum0 += __shfl_xor_sync(0xffffffffu, sum0, 2);
        sum1 += __shfl_xor_sync(0xffffffffu, sum1, 1);
        sum1 += __shfl_xor_sync(0xffffffffu, sum1, 2);
        l0 = l0 * f0 + sum0;
        l1 = l1 * f1 + sum1;

#pragma unroll
        for (int ni = 0; ni < 8; ni++) {
            o[ni][0] *= f0; o[ni][1] *= f0;
            o[ni][2] *= f1; o[ni][3] *= f1;
        }
        __syncwarp();

        // ---- O += P * V; P perm-token -> LDS.64 A-frags ----
        const uint32_t* Vb = Vsb[cur];
#pragma unroll
        for (int s = 0; s < 8; s++) {
            const int kk = s * 8;
            uint32_t af[4];
            const uint2 pa = *reinterpret_cast<const uint2*>(
                Psu + (mrow + gid) * AST + kk + 2 * tig);
            const uint2 pb = *reinterpret_cast<const uint2*>(
                Psu + (mrow + gid + 8) * AST + kk + 2 * tig);
            af[0] = pa.x; af[1] = pb.x;
            af[2] = pa.y; af[3] = pb.y;
            uint32_t bf[8][2];
#pragma unroll
            for (int ni = 0; ni < 8; ni++) {
                const uint32_t* q = Vb + (kk + tig) * AST + ni * 8 + gid;
                bf[ni][0] = q[0];
                bf[ni][1] = q[4 * AST];
            }
#pragma unroll
            for (int ni = 0; ni < 8; ni++)
                mma8(o[ni], af, bf[ni]);
        }
        __syncthreads();
    }

    // ---- finalize (cols are V's stored = permuted head positions, which is
    // exactly the layout o_proj expects for its contraction) ----
    {
        const float inv0 = 1.f / l0;
        const float inv1 = 1.f / l1;
        const int r0 = q0 + mrow + gid;
        uint32_t* Ou = (uint32_t*)(Og + base);
#pragma unroll
        for (int ni = 0; ni < 8; ni++) {
            const int cc = ni * 8 + 2 * tig;
            uint2 oa, ob;
            oa.x = tf32r(o[ni][0] * inv0);
            oa.y = tf32r(o[ni][1] * inv0);
            ob.x = tf32r(o[ni][2] * inv1);
            ob.y = tf32r(o[ni][3] * inv1);
            *reinterpret_cast<uint2*>(Ou + (size_t)r0 * HDc + cc) = oa;
            *reinterpret_cast<uint2*>(Ou + (size_t)(r0 + 8) * HDc + cc) = ob;
        }
    }
}

// ---------------------------------------------------------------------------
extern "C" void kernel_launch(void* const* d_in, const int* in_sizes, int n_in,
                              void* d_out, int out_size)
{
    const float* q  = (const float*)d_in[0];
    const float* k  = (const float*)d_in[1];
    const float* v  = (const float*)d_in[2];
    // d_in[3] = mask (tril; causality applied analytically)
    const float* Wq = (const float*)d_in[4];
    const float* bq = (const float*)d_in[5];
    const float* Wk = (const float*)d_in[6];
    const float* bk = (const float*)d_in[7];
    const float* Wv = (const float*)d_in[8];
    const float* bv = (const float*)d_in[9];
    const float* Wo = (const float*)d_in[10];
    const float* bo = (const float*)d_in[11];
    float* out = (float*)d_out;

    float *qh, *kh, *vh, *ao, *qt, *kt, *vt, *wq, *wk, *wv, *wo;
    cudaGetSymbolAddress((void**)&qh, g_qh);
    cudaGetSymbolAddress((void**)&kh, g_kh);
    cudaGetSymbolAddress((void**)&vh, g_vh);
    cudaGetSymbolAddress((void**)&ao, g_ao);
    cudaGetSymbolAddress((void**)&qt, g_qt);
    cudaGetSymbolAddress((void**)&kt, g_kt);
    cudaGetSymbolAddress((void**)&vt, g_vt);
    cudaGetSymbolAddress((void**)&wq, g_wq);
    cudaGetSymbolAddress((void**)&wk, g_wk);
    cudaGetSymbolAddress((void**)&wv, g_wv);
    cudaGetSymbolAddress((void**)&wo, g_wo);

    static int cfg = 0;
    if (!cfg) {
        cudaFuncSetAttribute(qkv_proj,
            cudaFuncAttributeMaxDynamicSharedMemorySize, PROJ_SMEM);
        cudaFuncSetAttribute(o_proj,
            cudaFuncAttributeMaxDynamicSharedMemorySize, PROJ_SMEM);
        cudaFuncSetAttribute(attn2,
            cudaFuncAttributeMaxDynamicSharedMemorySize, ATT_SMEM);
        cfg = 1;
    }

    // tf32 + perm-k conversion, one launch (inputs: 512K groups; weights: 128K)
    const int blocks_x = (Mrows * DIMd / 8 + 255) / 256;  // 2048
    cvt_all<<<dim3(blocks_x, 1, 7), 256>>>(
        (const float4*)q, (const float4*)k, (const float4*)v,
        (const float4*)Wq, (const float4*)Wk, (const float4*)Wv, (const float4*)Wo,
        (float4*)qt, (float4*)kt, (float4*)vt,
        (float4*)wq, (float4*)wk, (float4*)wv, (float4*)wo);

    // Fused QKV projections (Q pre-scaled by ATTN_SCALE in epilogue)
    qkv_proj<<<dim3(DIMd / 128, Mrows / 128, 3), 256, PROJ_SMEM>>>(
        qt, kt, vt, wq, wk, wv, bq, bk, bv, qh, kh, vh);

    // Attention: 64 q-rows per CTA, heavy tiles first
    attn2<<<dim3(Nn / 64, Bb * Hh), 128, ATT_SMEM>>>(qh, kh, vh, ao);

    // Output projection
    o_proj<<<dim3(DIMd / 128, Mrows / 128), 256, PROJ_SMEM>>>(ao, wo, bo, out);
}

// round 9
// speedup vs baseline: 1.3000x; 1.1343x over previous
#include <cuda_runtime.h>
#include <math.h>
#include <stdint.h>

constexpr int Bb   = 2;
constexpr int Hh   = 16;
constexpr int Nn   = 2048;
constexpr int HDc  = 64;
constexpr int DIMd = 1024;
constexpr int Mrows = Bb * Nn;       // 4096
constexpr float ATTN_SCALE = 0.125f;

// k-group permutation: storage position 2t holds logical k t, 2t+1 holds t+4.
// Applied to every contraction dimension so mma fragments load as 64-bit pairs.

// Scratch buffers
__device__ float g_qh[Bb * Hh * Nn * HDc];   // Q heads (tf32, perm head dim, pre-scaled)
__device__ float g_kh[Bb * Hh * Nn * HDc];   // K heads (tf32, perm head dim)
__device__ float g_vh[Bb * Hh * Nn * HDc];   // V heads (tf32, perm head dim)
__device__ float g_ao[Bb * Hh * Nn * HDc];   // attn out (tf32, perm head dim)
__device__ float g_qt[Mrows * DIMd];         // tf32 perm-k copies of inputs
__device__ float g_kt[Mrows * DIMd];
__device__ float g_vt[Mrows * DIMd];
__device__ float g_wq[DIMd * DIMd];          // tf32 perm-k copies of weights
__device__ float g_wk[DIMd * DIMd];
__device__ float g_wv[DIMd * DIMd];
__device__ float g_wo[DIMd * DIMd];

__device__ __forceinline__ uint32_t tf32r(float x) {
    uint32_t y;
    asm("cvt.rna.tf32.f32 %0, %1;" : "=r"(y) : "f"(x));
    return y;
}

__device__ __forceinline__ void mma8(float* d, const uint32_t* a, const uint32_t* b) {
    asm volatile(
        "mma.sync.aligned.m16n8k8.row.col.f32.tf32.tf32.f32 "
        "{%0,%1,%2,%3}, {%4,%5,%6,%7}, {%8,%9}, {%0,%1,%2,%3};\n"
        : "+f"(d[0]), "+f"(d[1]), "+f"(d[2]), "+f"(d[3])
        : "r"(a[0]), "r"(a[1]), "r"(a[2]), "r"(a[3]), "r"(b[0]), "r"(b[1]));
}

__device__ __forceinline__ void cp16(uint32_t daddr, const void* src) {
    asm volatile("cp.async.cg.shared.global [%0], [%1], 16;\n"
                 :: "r"(daddr), "l"(src));
}
__device__ __forceinline__ void cp_commit() {
    asm volatile("cp.async.commit_group;\n");
}
template <int N>
__device__ __forceinline__ void cp_wait() {
    asm volatile("cp.async.wait_group %0;\n" :: "n"(N));
}

// ---------------------------------------------------------------------------
// Fused tf32 (RNA) conversion + k-group permute. Each thread handles one
// 8-wide k-group: out[0..7] = {in0,in4,in1,in5,in2,in6,in3,in7} (tf32).
// ---------------------------------------------------------------------------
__global__ __launch_bounds__(256) void cvt_all(
    const float4* q, const float4* k, const float4* v,
    const float4* wq, const float4* wk, const float4* wv, const float4* wo,
    float4* qt, float4* kt, float4* vt,
    float4* dwq, float4* dwk, float4* dwv, float4* dwo)
{
    const int z = blockIdx.z;
    const int n8 = (z < 3) ? (Mrows * DIMd / 8) : (DIMd * DIMd / 8);
    const int i = blockIdx.x * 256 + threadIdx.x;
    if (i >= n8) return;
    const float4* s;
    float4* d;
    switch (z) {
        case 0: s = q;  d = qt;  break;
        case 1: s = k;  d = kt;  break;
        case 2: s = v;  d = vt;  break;
        case 3: s = wq; d = dwq; break;
        case 4: s = wk; d = dwk; break;
        case 5: s = wv; d = dwv; break;
        default: s = wo; d = dwo; break;
    }
    const float4 a = s[2 * i];       // logical k 0..3
    const float4 b = s[2 * i + 1];   // logical k 4..7
    float4 o0, o1;
    o0.x = __uint_as_float(tf32r(a.x)); o0.y = __uint_as_float(tf32r(b.x));
    o0.z = __uint_as_float(tf32r(a.y)); o0.w = __uint_as_float(tf32r(b.y));
    o1.x = __uint_as_float(tf32r(a.z)); o1.y = __uint_as_float(tf32r(b.z));
    o1.z = __uint_as_float(tf32r(a.w)); o1.w = __uint_as_float(tf32r(b.w));
    d[2 * i]     = o0;
    d[2 * i + 1] = o1;
}

// ---------------------------------------------------------------------------
// Projection GEMM: 128x128x32 tiles, 2-stage cp.async double buffer,
// 81.9KB smem, __launch_bounds__(256,2) -> regs<=128 -> 2 CTAs/SM.
// 256 threads, 8 warps (2x4), 64x32 per warp, perm-k LDS.64 fragments.
// ---------------------------------------------------------------------------
constexpr int SKA = 40;                        // smem k-stride words
constexpr int PROJ_SMEM = 4 * 128 * SKA * 4;   // 81920 B

template <bool SPLIT_IN, bool SPLIT_OUT, bool ROUND>
__device__ __forceinline__ void proj_body(
    const float* __restrict__ A, const float* __restrict__ W,
    const float* __restrict__ bias, float* __restrict__ C, float scale,
    float* smf)
{
    const int m0 = blockIdx.y * 128, n0 = blockIdx.x * 128;
    const int tid = threadIdx.x;
    const int w = tid >> 5, lane = tid & 31;
    const int gid = lane >> 2, tig = lane & 3;
    const int mbase = (w & 1) * 64;
    const int nbase = (w >> 1) * 32;

    const uint32_t* Asb[2] = {(const uint32_t*)smf,
                              (const uint32_t*)smf + 128 * SKA};
    const uint32_t* Wsb[2] = {(const uint32_t*)smf + 2 * 128 * SKA,
                              (const uint32_t*)smf + 3 * 128 * SKA};
    const uint32_t su = (uint32_t)__cvta_generic_to_shared(smf);
    const uint32_t asu[2] = {su, su + 128 * SKA * 4};
    const uint32_t wsu[2] = {su + 2 * 128 * SKA * 4, su + 3 * 128 * SKA * 4};

    auto load_tiles = [&](int kt, int buf) {
        const int k0 = kt * 32;
#pragma unroll
        for (int t = 0; t < 4; t++) {
            const int idx = tid + t * 256;
            const int r = idx >> 3, c = (idx & 7) << 2;
            const float* ap;
            if (SPLIT_IN) {
                const int gm = m0 + r, gk = k0 + c;
                const int b = gm >> 11, tok = gm & (Nn - 1);
                const int h = gk >> 6, cc = gk & 63;
                ap = A + ((size_t)((b * Hh + h) * Nn + tok)) * HDc + cc;
            } else {
                ap = A + (size_t)(m0 + r) * DIMd + k0 + c;
            }
            cp16(asu[buf] + (r * SKA + c) * 4, ap);
            cp16(wsu[buf] + (r * SKA + c) * 4,
                 W + (size_t)(n0 + r) * DIMd + k0 + c);
        }
        cp_commit();
    };

    float c[4][4][4];
#pragma unroll
    for (int mi = 0; mi < 4; mi++)
#pragma unroll
        for (int ni = 0; ni < 4; ni++)
#pragma unroll
            for (int u = 0; u < 4; u++) c[mi][ni][u] = 0.f;

    load_tiles(0, 0);
    constexpr int ITERS = DIMd / 32;  // 32
    for (int kt = 0; kt < ITERS; kt++) {
        const int cur = kt & 1;
        if (kt + 1 < ITERS) { load_tiles(kt + 1, cur ^ 1); cp_wait<1>(); }
        else                { cp_wait<0>(); }
        __syncthreads();

        const uint32_t* Ab = Asb[cur];
        const uint32_t* Wb = Wsb[cur];
#pragma unroll
        for (int kk = 0; kk < 32; kk += 8) {
            uint32_t af[4][4];
#pragma unroll
            for (int mi = 0; mi < 4; mi++) {
                const int row = mbase + mi * 16 + gid;
                const uint2 a0 = *reinterpret_cast<const uint2*>(
                    Ab + row * SKA + kk + 2 * tig);
                const uint2 a1 = *reinterpret_cast<const uint2*>(
                    Ab + (row + 8) * SKA + kk + 2 * tig);
                af[mi][0] = a0.x; af[mi][1] = a1.x;
                af[mi][2] = a0.y; af[mi][3] = a1.y;
            }
            uint32_t bf[4][2];
#pragma unroll
            for (int ni = 0; ni < 4; ni++) {
                const uint2 b = *reinterpret_cast<const uint2*>(
                    Wb + (nbase + ni * 8 + gid) * SKA + kk + 2 * tig);
                bf[ni][0] = b.x;
                bf[ni][1] = b.y;
            }
#pragma unroll
            for (int mi = 0; mi < 4; mi++)
#pragma unroll
                for (int ni = 0; ni < 4; ni++)
                    mma8(c[mi][ni], af[mi], bf[ni]);
        }
        __syncthreads();
    }

    // Epilogue. Logical cols c0=2tig, c1=2tig+1; permuted positions
    // p0 = {0,4,1,5}[tig], p1 = p0+2 (only used when SPLIT_OUT feeds attn).
    const int p0 = (tig < 2) ? 4 * tig : 4 * tig - 7;
#pragma unroll
    for (int mi = 0; mi < 4; mi++) {
#pragma unroll
        for (int ni = 0; ni < 4; ni++) {
            const int nlog = n0 + nbase + ni * 8 + 2 * tig;
            const float bx = bias[nlog], by = bias[nlog + 1];
#pragma unroll
            for (int hr = 0; hr < 2; hr++) {
                const int m = m0 + mbase + mi * 16 + gid + hr * 8;
                float ox = (c[mi][ni][hr * 2 + 0] + bx) * scale;
                float oy = (c[mi][ni][hr * 2 + 1] + by) * scale;
                if (ROUND) {
                    ox = __uint_as_float(tf32r(ox));
                    oy = __uint_as_float(tf32r(oy));
                }
                if (SPLIT_OUT) {
                    const int b = m >> 11, tok = m & (Nn - 1);
                    const int np0 = n0 + nbase + ni * 8 + p0;
                    const int h = np0 >> 6;
                    float* dst = C + ((size_t)((b * Hh + h) * Nn + tok)) * HDc;
                    dst[np0 & 63]       = ox;
                    dst[(np0 + 2) & 63] = oy;
                } else {
                    float2 o; o.x = ox; o.y = oy;
                    *reinterpret_cast<float2*>(C + (size_t)m * DIMd + nlog) = o;
                }
            }
        }
    }
}

__global__ __launch_bounds__(256, 2) void qkv_proj(
    const float* aq, const float* ak, const float* av,
    const float* wq, const float* wk, const float* wv,
    const float* bq, const float* bk, const float* bv,
    float* cq, float* ck, float* cv)
{
    extern __shared__ float smf[];
    const int z = blockIdx.z;
    const float* A = (z == 0) ? aq : (z == 1) ? ak : av;
    const float* W = (z == 0) ? wq : (z == 1) ? wk : wv;
    const float* b = (z == 0) ? bq : (z == 1) ? bk : bv;
    float*       C = (z == 0) ? cq : (z == 1) ? ck : cv;
    const float scale = (z == 0) ? ATTN_SCALE : 1.0f;
    proj_body<false, true, true>(A, W, b, C, scale, smf);
}

__global__ __launch_bounds__(256, 2) void o_proj(
    const float* A, const float* W, const float* b, float* C)
{
    extern __shared__ float smf[];
    proj_body<true, false, false>(A, W, b, C, 1.0f, smf);
}

// ---------------------------------------------------------------------------
// Causal flash attention: 64 q-rows/CTA, 128 threads (4 warps, 16x64 strips),
// register softmax, cp.async double buffer with true overlap, heavy-first.
// Head dim perm-k (LDS.64 K frags, LDG.64 Q frags); P stored perm-token
// (LDS.64 P frags). AST=72 ≡ 8 mod 32.
// ---------------------------------------------------------------------------
constexpr int AST = 72;  // smem row stride (words)
constexpr int ATT_SMEM = 5 * 64 * AST * 4;  // 2xK, 2xV, P = 92160 B

__global__ __launch_bounds__(128) void attn2(
    const float* __restrict__ Qg, const float* __restrict__ Kg,
    const float* __restrict__ Vg, float* __restrict__ Og)
{
    extern __shared__ float smf[];
    const uint32_t su = (uint32_t)__cvta_generic_to_shared(smf);
    const uint32_t ksu[2] = {su, su + 64 * AST * 4};
    const uint32_t vsu[2] = {su + 2 * 64 * AST * 4, su + 3 * 64 * AST * 4};
    const uint32_t* Ksb[2] = {(const uint32_t*)smf,
                              (const uint32_t*)smf + 64 * AST};
    const uint32_t* Vsb[2] = {(const uint32_t*)smf + 2 * 64 * AST,
                              (const uint32_t*)smf + 3 * 64 * AST};
    uint32_t* Psu = (uint32_t*)smf + 4 * 64 * AST;

    const int bh = blockIdx.y;
    const int qt = (gridDim.x - 1) - blockIdx.x;   // heavy-first
    const int q0 = qt * 64;
    const size_t base = (size_t)bh * Nn * HDc;

    const int tid = threadIdx.x;
    const int w = tid >> 5, lane = tid & 31;
    const int gid = lane >> 2, tig = lane & 3;
    const int mrow = w * 16;
    const int p0 = (tig < 2) ? 4 * tig : 4 * tig - 7;  // perm pos of col 2tig

    auto issueKV = [&](int t_kt, int buf) {
        const float* Kb = Kg + base + (size_t)(t_kt * 64) * HDc;
        const float* Vb = Vg + base + (size_t)(t_kt * 64) * HDc;
#pragma unroll
        for (int t = 0; t < 8; t++) {
            const int idx = tid + t * 128;
            const int r = idx >> 4, cc = (idx & 15) << 2;
            cp16(ksu[buf] + (r * AST + cc) * 4, Kb + r * HDc + cc);
            cp16(vsu[buf] + (r * AST + cc) * 4, Vb + r * HDc + cc);
        }
        cp_commit();
    };

    // Q fragments from perm-k qh: 64-bit pairs at 2tig
    uint32_t qf[8][4];
    {
        const uint32_t* Qu = (const uint32_t*)(Qg + base) +
                             (size_t)(q0 + mrow + gid) * HDc;
#pragma unroll
        for (int s = 0; s < 8; s++) {
            const uint2 u0 = *reinterpret_cast<const uint2*>(Qu + s * 8 + 2 * tig);
            const uint2 u1 = *reinterpret_cast<const uint2*>(Qu + 8 * HDc + s * 8 + 2 * tig);
            qf[s][0] = u0.x; qf[s][1] = u1.x;
            qf[s][2] = u0.y; qf[s][3] = u1.y;
        }
    }

    float o[8][4];
#pragma unroll
    for (int ni = 0; ni < 8; ni++)
#pragma unroll
        for (int u = 0; u < 4; u++) o[ni][u] = 0.f;
    float m0r = -1e30f, m1r = -1e30f, l0 = 0.f, l1 = 0.f;

    issueKV(0, 0);

    for (int kt = 0; kt <= qt; kt++) {
        const int cur = kt & 1;
        if (kt < qt) { issueKV(kt + 1, cur ^ 1); cp_wait<1>(); }
        else         { cp_wait<0>(); }
        __syncthreads();

        // ---- S = Q K^T (16x64 per warp); K head dim perm -> LDS.64 ----
        float s4[8][4];
#pragma unroll
        for (int ni = 0; ni < 8; ni++)
#pragma unroll
            for (int u = 0; u < 4; u++) s4[ni][u] = 0.f;

        const uint32_t* Kb = Ksb[cur];
#pragma unroll
        for (int s = 0; s < 8; s++) {
            const int kk = s * 8;
            uint32_t bf[8][2];
#pragma unroll
            for (int ni = 0; ni < 8; ni++) {
                const uint2 b = *reinterpret_cast<const uint2*>(
                    Kb + (ni * 8 + gid) * AST + kk + 2 * tig);
                bf[ni][0] = b.x;
                bf[ni][1] = b.y;
            }
#pragma unroll
            for (int ni = 0; ni < 8; ni++)
                mma8(s4[ni], qf[s], bf[ni]);
        }

        // ---- causal mask (diagonal tile only; token cols are logical) ----
        if (kt == qt) {
            const int r0 = q0 + mrow + gid, r1 = r0 + 8;
            const int k0 = kt * 64;
#pragma unroll
            for (int ni = 0; ni < 8; ni++) {
                const int cc = k0 + ni * 8 + 2 * tig;
                if (cc > r0)     s4[ni][0] = -1e30f;
                if (cc + 1 > r0) s4[ni][1] = -1e30f;
                if (cc > r1)     s4[ni][2] = -1e30f;
                if (cc + 1 > r1) s4[ni][3] = -1e30f;
            }
        }

        // ---- register softmax ----
        float mx0 = -1e30f, mx1 = -1e30f;
#pragma unroll
        for (int ni = 0; ni < 8; ni++) {
            mx0 = fmaxf(mx0, fmaxf(s4[ni][0], s4[ni][1]));
            mx1 = fmaxf(mx1, fmaxf(s4[ni][2], s4[ni][3]));
        }
        mx0 = fmaxf(mx0, __shfl_xor_sync(0xffffffffu, mx0, 1));
        mx0 = fmaxf(mx0, __shfl_xor_sync(0xffffffffu, mx0, 2));
        mx1 = fmaxf(mx1, __shfl_xor_sync(0xffffffffu, mx1, 1));
        mx1 = fmaxf(mx1, __shfl_xor_sync(0xffffffffu, mx1, 2));
        const float mn0 = fmaxf(m0r, mx0);
        const float mn1 = fmaxf(m1r, mx1);
        const float f0 = __expf(m0r - mn0);
        const float f1 = __expf(m1r - mn1);
        m0r = mn0; m1r = mn1;

        // P written with perm-token positions: col 2tig -> p0, 2tig+1 -> p0+2
        float sum0 = 0.f, sum1 = 0.f;
        uint32_t* PwA = Psu + (mrow + gid) * AST;
        uint32_t* PwB = PwA + 8 * AST;
#pragma unroll
        for (int ni = 0; ni < 8; ni++) {
            const float e0 = __expf(s4[ni][0] - mn0);
            const float e1 = __expf(s4[ni][1] - mn0);
            const float e2 = __expf(s4[ni][2] - mn1);
            const float e3 = __expf(s4[ni][3] - mn1);
            sum0 += e0 + e1;
            sum1 += e2 + e3;
            PwA[ni * 8 + p0]     = tf32r(e0);
            PwA[ni * 8 + p0 + 2] = tf32r(e1);
            PwB[ni * 8 + p0]     = tf32r(e2);
            PwB[ni * 8 + p0 + 2] = tf32r(e3);
        }
        sum0 += __shfl_xor_sync(0xffffffffu, sum0, 1);
        sum0 += __shfl_xor_sync(0xffffffffu, sum0, 2);
        sum1 += __shfl_xor_sync(0xffffffffu, sum1, 1);
        sum1 += __shfl_xor_sync(0xffffffffu, sum1, 2);
        l0 = l0 * f0 + sum0;
        l1 = l1 * f1 + sum1;

#pragma unroll
        for (int ni = 0; ni < 8; ni++) {
            o[ni][0] *= f0; o[ni][1] *= f0;
            o[ni][2] *= f1; o[ni][3] *= f1;
        }
        __syncwarp();

        // ---- O += P * V; P perm-token -> LDS.64 A-frags ----
        const uint32_t* Vb = Vsb[cur];
#pragma unroll
        for (int s = 0; s < 8; s++) {
            const int kk = s * 8;
            uint32_t af[4];
            const uint2 pa = *reinterpret_cast<const uint2*>(
                Psu + (mrow + gid) * AST + kk + 2 * tig);
            const uint2 pb = *reinterpret_cast<const uint2*>(
                Psu + (mrow + gid + 8) * AST + kk + 2 * tig);
            af[0] = pa.x; af[1] = pb.x;
            af[2] = pa.y; af[3] = pb.y;
            uint32_t bf[8][2];
#pragma unroll
            for (int ni = 0; ni < 8; ni++) {
                const uint32_t* q = Vb + (kk + tig) * AST + ni * 8 + gid;
                bf[ni][0] = q[0];
                bf[ni][1] = q[4 * AST];
            }
#pragma unroll
            for (int ni = 0; ni < 8; ni++)
                mma8(o[ni], af, bf[ni]);
        }
        __syncthreads();
    }

    // ---- finalize (cols are V's stored = permuted head positions, which is
    // exactly the layout o_proj expects for its contraction) ----
    {
        const float inv0 = 1.f / l0;
        const float inv1 = 1.f / l1;
        const int r0 = q0 + mrow + gid;
        uint32_t* Ou = (uint32_t*)(Og + base);
#pragma unroll
        for (int ni = 0; ni < 8; ni++) {
            const int cc = ni * 8 + 2 * tig;
            uint2 oa, ob;
            oa.x = tf32r(o[ni][0] * inv0);
            oa.y = tf32r(o[ni][1] * inv0);
            ob.x = tf32r(o[ni][2] * inv1);
            ob.y = tf32r(o[ni][3] * inv1);
            *reinterpret_cast<uint2*>(Ou + (size_t)r0 * HDc + cc) = oa;
            *reinterpret_cast<uint2*>(Ou + (size_t)(r0 + 8) * HDc + cc) = ob;
        }
    }
}

// ---------------------------------------------------------------------------
extern "C" void kernel_launch(void* const* d_in, const int* in_sizes, int n_in,
                              void* d_out, int out_size)
{
    const float* q  = (const float*)d_in[0];
    const float* k  = (const float*)d_in[1];
    const float* v  = (const float*)d_in[2];
    // d_in[3] = mask (tril; causality applied analytically)
    const float* Wq = (const float*)d_in[4];
    const float* bq = (const float*)d_in[5];
    const float* Wk = (const float*)d_in[6];
    const float* bk = (const float*)d_in[7];
    const float* Wv = (const float*)d_in[8];
    const float* bv = (const float*)d_in[9];
    const float* Wo = (const float*)d_in[10];
    const float* bo = (const float*)d_in[11];
    float* out = (float*)d_out;

    float *qh, *kh, *vh, *ao, *qt, *kt, *vt, *wq, *wk, *wv, *wo;
    cudaGetSymbolAddress((void**)&qh, g_qh);
    cudaGetSymbolAddress((void**)&kh, g_kh);
    cudaGetSymbolAddress((void**)&vh, g_vh);
    cudaGetSymbolAddress((void**)&ao, g_ao);
    cudaGetSymbolAddress((void**)&qt, g_qt);
    cudaGetSymbolAddress((void**)&kt, g_kt);
    cudaGetSymbolAddress((void**)&vt, g_vt);
    cudaGetSymbolAddress((void**)&wq, g_wq);
    cudaGetSymbolAddress((void**)&wk, g_wk);
    cudaGetSymbolAddress((void**)&wv, g_wv);
    cudaGetSymbolAddress((void**)&wo, g_wo);

    static int cfg = 0;
    if (!cfg) {
        cudaFuncSetAttribute(qkv_proj,
            cudaFuncAttributeMaxDynamicSharedMemorySize, PROJ_SMEM);
        cudaFuncSetAttribute(o_proj,
            cudaFuncAttributeMaxDynamicSharedMemorySize, PROJ_SMEM);
        cudaFuncSetAttribute(attn2,
            cudaFuncAttributeMaxDynamicSharedMemorySize, ATT_SMEM);
        cfg = 1;
    }

    // tf32 + perm-k conversion, one launch
    const int blocks_x = (Mrows * DIMd / 8 + 255) / 256;  // 2048
    cvt_all<<<dim3(blocks_x, 1, 7), 256>>>(
        (const float4*)q, (const float4*)k, (const float4*)v,
        (const float4*)Wq, (const float4*)Wk, (const float4*)Wv, (const float4*)Wo,
        (float4*)qt, (float4*)kt, (float4*)vt,
        (float4*)wq, (float4*)wk, (float4*)wv, (float4*)wo);

    // Fused QKV projections (Q pre-scaled by ATTN_SCALE in epilogue)
    qkv_proj<<<dim3(DIMd / 128, Mrows / 128, 3), 256, PROJ_SMEM>>>(
        qt, kt, vt, wq, wk, wv, bq, bk, bv, qh, kh, vh);

    // Attention: 64 q-rows per CTA, heavy tiles first
    attn2<<<dim3(Nn / 64, Bb * Hh), 128, ATT_SMEM>>>(qh, kh, vh, ao);

    // Output projection
    o_proj<<<dim3(DIMd / 128, Mrows / 128), 256, PROJ_SMEM>>>(ao, wo, bo, out);
}